// round 13
// baseline (speedup 1.0000x reference)
#include <cuda_runtime.h>
#include <cuda_fp16.h>
#include <stdint.h>

#define B_  4
#define S_  1024
#define D_  1024
#define H_  16
#define HD_ 64
#define M_  (B_ * S_)     // 4096

// ---------------------------------------------------------------------------
// Scratch (device globals)
// ---------------------------------------------------------------------------
__device__ __align__(16) __half g_Xh   [(size_t)M_ * D_];
__device__ __align__(16) __half g_Wqkvh[(size_t)3 * D_ * D_];
__device__ __align__(16) __half g_W1h  [(size_t)2 * D_ * D_];
__device__ __align__(16) __half g_W2h  [(size_t)2 * D_ * D_];
__device__ __align__(16) __half g_QKVh [(size_t)M_ * 3 * D_];    // Q,K permuted; V plain
__device__ __align__(16) __half g_Ch   [(size_t)M_ * D_];
__device__ __align__(16) __half g_Hh   [(size_t)M_ * 2 * D_];
__device__ __align__(16) float  g_bqkv [3 * D_];
__device__ int g_mflag[B_ * (S_ / 128) * (S_ / 64)];

// ---------------------------------------------------------------------------
__device__ __forceinline__ void mma_f16(float* c, const uint32_t* a, const uint32_t* b) {
    asm volatile(
        "mma.sync.aligned.m16n8k16.row.col.f32.f16.f16.f32 "
        "{%0,%1,%2,%3}, {%4,%5,%6,%7}, {%8,%9}, {%0,%1,%2,%3};\n"
        : "+f"(c[0]), "+f"(c[1]), "+f"(c[2]), "+f"(c[3])
        : "r"(a[0]), "r"(a[1]), "r"(a[2]), "r"(a[3]), "r"(b[0]), "r"(b[1]));
}

__device__ __forceinline__ void ldsm_x4(uint32_t& r0, uint32_t& r1,
                                        uint32_t& r2, uint32_t& r3, uint32_t addr) {
    asm volatile("ldmatrix.sync.aligned.m8n8.x4.shared.b16 {%0,%1,%2,%3}, [%4];"
                 : "=r"(r0), "=r"(r1), "=r"(r2), "=r"(r3) : "r"(addr));
}

__device__ __forceinline__ void ldsm_x4_t(uint32_t& r0, uint32_t& r1,
                                          uint32_t& r2, uint32_t& r3, uint32_t addr) {
    asm volatile("ldmatrix.sync.aligned.m8n8.x4.trans.shared.b16 {%0,%1,%2,%3}, [%4];"
                 : "=r"(r0), "=r"(r1), "=r"(r2), "=r"(r3) : "r"(addr));
}

__device__ __forceinline__ uint32_t smem_u32(const void* p) {
    uint32_t a;
    asm("{ .reg .u64 t; cvta.to.shared.u64 t, %1; cvt.u32.u64 %0, t; }"
        : "=r"(a) : "l"(p));
    return a;
}

__device__ __forceinline__ void cp_async16(uint32_t dst, const void* src) {
    asm volatile("cp.async.cg.shared.global [%0], [%1], 16;"
                 :: "r"(dst), "l"(src) : "memory");
}

__device__ __forceinline__ uint32_t packh2(float x, float y) {
    __half2 h = __floats2half2_rn(x, y);
    return *(uint32_t*)&h;
}

__device__ __forceinline__ int permn(int n0) {
    return (n0 & ~15) | (((n0 >> 1) & 3) << 2) | ((n0 & 8) >> 2);
}

// ---------------------------------------------------------------------------
// Prep kernels
// ---------------------------------------------------------------------------
struct HSegs {
    const float* src[6];
    __half*      dst[6];
    int          cum[7];
};

__global__ void round_half_all(HSegs P) {
    const int i = blockIdx.x * blockDim.x + threadIdx.x;
    if (i >= P.cum[6]) return;
#pragma unroll
    for (int j = 0; j < 6; j++) {
        if (i < P.cum[j + 1]) {
            const int g = i - P.cum[j];
            const float4* s = (const float4*)P.src[j] + (size_t)g * 4;
            float l[16];
            *(float4*)&l[0]  = s[0];
            *(float4*)&l[4]  = s[1];
            *(float4*)&l[8]  = s[2];
            *(float4*)&l[12] = s[3];
            uint4 o0, o1;
            o0.x = packh2(l[0],  l[1]);  o0.y = packh2(l[2],  l[3]);
            o0.z = packh2(l[4],  l[5]);  o0.w = packh2(l[6],  l[7]);
            o1.x = packh2(l[8],  l[9]);  o1.y = packh2(l[10], l[11]);
            o1.z = packh2(l[12], l[13]); o1.w = packh2(l[14], l[15]);
            uint4* d = (uint4*)(P.dst[j] + (size_t)g * 16);
            d[0] = o0; d[1] = o1;
            return;
        }
    }
}

__global__ void concat_bias(const float* __restrict__ a, const float* __restrict__ b,
                            const float* __restrict__ c, float* __restrict__ dst) {
    const int i = blockIdx.x * blockDim.x + threadIdx.x;
    if (i < 3 * D_)
        dst[i] = (i < D_) ? a[i] : ((i < 2 * D_) ? b[i - D_] : c[i - 2 * D_]);
}

__global__ __launch_bounds__(256)
void mask_scan(const int* __restrict__ mask, int* __restrict__ flags) {
    const int fidx = blockIdx.x;
    const int kt = fidx & 15;
    const int qt = (fidx >> 4) & 7;
    const int b  = fidx >> 7;
    const int q0 = qt * 128;
    const int k0 = kt * 64;
    const int tid = threadIdx.x;

    int ok = 1;
#pragma unroll
    for (int i = 0; i < 8; i++) {
        const int idx = tid + 256 * i;
        const int row = idx >> 4;
        const int c4  = (idx & 15) * 4;
        const int4 v = *(const int4*)&mask[((size_t)(b * S_ + q0 + row)) * S_ + k0 + c4];
        if (v.x == 0 || v.y == 0 || v.z == 0 || v.w == 0) ok = 0;
    }
    const int all_ok = __syncthreads_and(ok);
    if (tid == 0) flags[fidx] = !all_ok;
}

// ---------------------------------------------------------------------------
// fp16 tensor-core GEMM: 128x128 tile, K-stage 64, 2-stage cp.async (3 CTA/SM),
// XOR-swizzled smem + ldmatrix fragment loads.
// ---------------------------------------------------------------------------
#define GROWB 128
#define GSTG_B (128 * GROWB)
#define GSTAGE_B (2 * GSTG_B)          // 32,768
#define GNST 2
#define HGEMM_SMEM (GNST * GSTAGE_B)   // 65,536

template <int MODE>
__global__ __launch_bounds__(256, 3)
void gemm_h(const __half* __restrict__ A, const __half* __restrict__ Bm,
            const float* __restrict__ bias, float* __restrict__ Cf,
            __half* __restrict__ Ch, int M, int N, int K)
{
    extern __shared__ __align__(16) char smc[];
    const uint32_t sb = smem_u32(smc);

    const int tid  = threadIdx.x;
    const int lane = tid & 31;
    const int wid  = tid >> 5;
    const int wm   = wid >> 2;
    const int wn   = wid & 3;
    const int grp  = lane >> 2;
    const int qid  = lane & 3;

    const int bm = blockIdx.y * 128;
    const int bn = blockIdx.x * 128;

    const __half* AgBase = A  + (size_t)bm * K;
    const __half* BgBase = Bm + (size_t)bn * K;

    auto issue_stage = [&](int stage, int buf) {
        const int k0 = stage * 64;
        const uint32_t sA = sb + (uint32_t)buf * GSTAGE_B;
        const uint32_t sB = sA + GSTG_B;
#pragma unroll
        for (int i = 0; i < 4; i++) {
            const int ci  = tid + 256 * i;
            const int row = ci >> 3;
            const int c   = ci & 7;
            cp_async16(sA + (uint32_t)row * GROWB + (uint32_t)((c ^ (row & 7)) << 4),
                       AgBase + (size_t)row * K + k0 + c * 8);
        }
#pragma unroll
        for (int i = 0; i < 4; i++) {
            const int ci  = tid + 256 * i;
            const int row = ci >> 3;
            const int c   = ci & 7;
            cp_async16(sB + (uint32_t)row * GROWB + (uint32_t)((c ^ (row & 7)) << 4),
                       BgBase + (size_t)row * K + k0 + c * 8);
        }
        asm volatile("cp.async.commit_group;" ::: "memory");
    };

    float acc[4][4][4];
#pragma unroll
    for (int i = 0; i < 4; i++)
#pragma unroll
        for (int j = 0; j < 4; j++)
#pragma unroll
            for (int r = 0; r < 4; r++) acc[i][j][r] = 0.f;

    const int KT = K / 64;

    issue_stage(0, 0);
    issue_stage(1, 1);

    const int al8 = (lane & 7) + ((lane >> 3) & 1) * 8;
    const int ach = lane >> 4;
    const int bl8 = lane & 7;
    const int bg  = lane >> 3;

    for (int kt = 0; kt < KT; kt++) {
        const int buf = kt & 1;

        if (kt < KT - 1)
            asm volatile("cp.async.wait_group 1;" ::: "memory");
        else
            asm volatile("cp.async.wait_group 0;" ::: "memory");
        __syncthreads();

        const uint32_t sA = sb + (uint32_t)buf * GSTAGE_B;
        const uint32_t sB = sA + GSTG_B;

#pragma unroll
        for (int s = 0; s < 4; s++) {
            uint32_t a[4][4];
#pragma unroll
            for (int mf = 0; mf < 4; mf++) {
                const int arow = wm * 64 + mf * 16 + al8;
                const int c    = (s * 2 + ach) ^ (arow & 7);
                ldsm_x4(a[mf][0], a[mf][1], a[mf][2], a[mf][3],
                        sA + (uint32_t)arow * GROWB + (uint32_t)(c << 4));
            }
            uint32_t b[4][2];
#pragma unroll
            for (int nfp = 0; nfp < 2; nfp++) {
                const int brow = wn * 32 + nfp * 16 + (bg >> 1) * 8 + bl8;
                const int c    = (s * 2 + (bg & 1)) ^ (brow & 7);
                ldsm_x4(b[2 * nfp][0], b[2 * nfp][1], b[2 * nfp + 1][0], b[2 * nfp + 1][1],
                        sB + (uint32_t)brow * GROWB + (uint32_t)(c << 4));
            }
#pragma unroll
            for (int mf = 0; mf < 4; mf++)
#pragma unroll
                for (int nf = 0; nf < 4; nf++)
                    mma_f16(acc[mf][nf], a[mf], b[nf]);
        }

        // free this buffer for the stage-kt+2 loads
        __syncthreads();
        if (kt + 2 < KT)
            issue_stage(kt + 2, buf);
    }

    // ---- Epilogue ----
#pragma unroll
    for (int mf = 0; mf < 4; mf++) {
#pragma unroll
        for (int nf = 0; nf < 4; nf++) {
            const int m0 = bm + wm * 64 + mf * 16 + grp;
            const int n0 = bn + wn * 32 + nf * 8 + 2 * qid;
            const float bx = bias[n0], by = bias[n0 + 1];
            float2 v0, v1;
            v0.x = acc[mf][nf][0] + bx; v0.y = acc[mf][nf][1] + by;
            v1.x = acc[mf][nf][2] + bx; v1.y = acc[mf][nf][3] + by;

            if (MODE == 0) {
                if (n0 < D_) {
                    v0.x *= 0.125f; v0.y *= 0.125f;
                    v1.x *= 0.125f; v1.y *= 0.125f;
                }
                const int pn = (n0 < 2 * D_) ? permn(n0) : n0;
                *(uint32_t*)&Ch[(size_t)m0 * N + pn]       = packh2(v0.x, v0.y);
                *(uint32_t*)&Ch[(size_t)(m0 + 8) * N + pn] = packh2(v1.x, v1.y);
            } else if (MODE == 1) {
                v0.x = fmaxf(v0.x, 0.f); v0.y = fmaxf(v0.y, 0.f);
                v1.x = fmaxf(v1.x, 0.f); v1.y = fmaxf(v1.y, 0.f);
                *(uint32_t*)&Ch[(size_t)m0 * N + n0]       = packh2(v0.x, v0.y);
                *(uint32_t*)&Ch[(size_t)(m0 + 8) * N + n0] = packh2(v1.x, v1.y);
            } else {
                *(float2*)&Cf[(size_t)m0 * N + n0]       = v0;
                *(float2*)&Cf[(size_t)(m0 + 8) * N + n0] = v1;
            }
        }
    }
}

// ---------------------------------------------------------------------------
// fp16 tensor-core flash attention (R12) — now 3 CTAs/SM.
// ---------------------------------------------------------------------------
#define QT_ 128
#define QSTRB 160
#define KSTRB 160
#define VSTRB 144
#define QS_BYTES   (QT_ * QSTRB)
#define KSTG_BYTES (64 * KSTRB)
#define VSTG_BYTES (64 * VSTRB)
#define ATTN_SMEM_BYTES (QS_BYTES + 2 * KSTG_BYTES + 2 * VSTG_BYTES)  // 59,392

__global__ __launch_bounds__(256, 3)
void attn_h(const __half* __restrict__ QKV, const int* __restrict__ mask,
            const int* __restrict__ mflag, __half* __restrict__ O)
{
    extern __shared__ __align__(16) char smb[];
    const uint32_t sb  = smem_u32(smb);
    const uint32_t sQ  = sb;
    const uint32_t sK  = sb + QS_BYTES;
    const uint32_t sV  = sK + 2 * KSTG_BYTES;
    const char* Qsp = smb;
    const char* Ksp = smb + QS_BYTES;

    const int tid  = threadIdx.x;
    const int lane = tid & 31;
    const int wid  = tid >> 5;
    const int grp  = lane >> 2;
    const int qid  = lane & 3;

    const int qt = blockIdx.x;
    const int bh = blockIdx.y;
    const int b  = bh >> 4;
    const int h  = bh & 15;
    const int q0 = qt * QT_;

    const int LDQ = 3 * D_;
    const __half* Qb = QKV + (size_t)b * S_ * LDQ + (size_t)h * HD_;
    const __half* Kb = Qb + D_;
    const __half* Vb = Qb + 2 * D_;
    const int* mfbase = mflag + (b * (S_ / QT_) + qt) * (S_ / 64);

    auto issue_kv = [&](int kt, int buf) {
        const int k0g = kt * 64;
#pragma unroll
        for (int i = 0; i < 2; i++) {
            const int idx = tid + 256 * i;
            const int row = idx >> 3;
            const int ch  = idx & 7;
            cp_async16(sK + (uint32_t)buf * KSTG_BYTES + (uint32_t)row * KSTRB + ch * 16,
                       Kb + (size_t)(k0g + row) * LDQ + ch * 8);
            cp_async16(sV + (uint32_t)buf * VSTG_BYTES + (uint32_t)row * VSTRB + ch * 16,
                       Vb + (size_t)(k0g + row) * LDQ + ch * 8);
        }
        asm volatile("cp.async.commit_group;" ::: "memory");
    };

    issue_kv(0, 0);

#pragma unroll
    for (int i = 0; i < 4; i++) {
        const int idx = tid + 256 * i;
        const int row = idx >> 3;
        const int ch  = idx & 7;
        cp_async16(sQ + (uint32_t)row * QSTRB + ch * 16,
                   Qb + (size_t)(q0 + row) * LDQ + ch * 8);
    }
    asm volatile("cp.async.commit_group;" ::: "memory");

    const int qrow0 = wid * 16 + grp;
    const int* mrow0 = mask + (size_t)(b * S_ + q0 + qrow0) * S_;
    const int* mrow1 = mrow0 + 8 * S_;

    float mi0 = -1e30f, mi1 = -1e30f, li0 = 0.f, li1 = 0.f;
    float o[8][4];
#pragma unroll
    for (int nf = 0; nf < 8; nf++)
#pragma unroll
        for (int r = 0; r < 4; r++) o[nf][r] = 0.f;

    for (int kt = 0; kt < S_ / 64; kt++) {
        const int buf = kt & 1;
        const int k0  = kt * 64;
        const bool dirty = mfbase[kt] != 0;

        asm volatile("cp.async.wait_group 0;" ::: "memory");
        __syncthreads();

        if (kt + 1 < S_ / 64)
            issue_kv(kt + 1, buf ^ 1);

        const char* Kb2 = Ksp + (size_t)buf * KSTG_BYTES;
        const uint32_t Vb2 = sV + (uint32_t)buf * VSTG_BYTES;

        float c[8][4];
#pragma unroll
        for (int nf = 0; nf < 8; nf++)
#pragma unroll
            for (int r = 0; r < 4; r++) c[nf][r] = 0.f;

#pragma unroll
        for (int s = 0; s < 4; s++) {
            const uint2 lo = *(const uint2*)(Qsp + qrow0 * QSTRB + s * 32 + qid * 8);
            const uint2 hi = *(const uint2*)(Qsp + (qrow0 + 8) * QSTRB + s * 32 + qid * 8);
            uint32_t a[4] = { lo.x, hi.x, lo.y, hi.y };
#pragma unroll
            for (int nf = 0; nf < 8; nf++) {
                const uint2 bv = *(const uint2*)(Kb2 + (nf * 8 + grp) * KSTRB + s * 32 + qid * 8);
                uint32_t bb[2] = { bv.x, bv.y };
                mma_f16(c[nf], a, bb);
            }
        }

        if (dirty) {
#pragma unroll
            for (int nf = 0; nf < 8; nf++) {
                const int kc = k0 + nf * 8 + 2 * qid;
                const int2 m0 = *(const int2*)&mrow0[kc];
                const int2 m1 = *(const int2*)&mrow1[kc];
                if (m0.x == 0) c[nf][0] = -1e8f;
                if (m0.y == 0) c[nf][1] = -1e8f;
                if (m1.x == 0) c[nf][2] = -1e8f;
                if (m1.y == 0) c[nf][3] = -1e8f;
            }
        }

        float mx0 = -1e30f, mx1 = -1e30f;
#pragma unroll
        for (int nf = 0; nf < 8; nf++) {
            mx0 = fmaxf(mx0, fmaxf(c[nf][0], c[nf][1]));
            mx1 = fmaxf(mx1, fmaxf(c[nf][2], c[nf][3]));
        }
        mx0 = fmaxf(mx0, __shfl_xor_sync(0xffffffffu, mx0, 1));
        mx0 = fmaxf(mx0, __shfl_xor_sync(0xffffffffu, mx0, 2));
        mx1 = fmaxf(mx1, __shfl_xor_sync(0xffffffffu, mx1, 1));
        mx1 = fmaxf(mx1, __shfl_xor_sync(0xffffffffu, mx1, 2));

        const float mn0 = fmaxf(mi0, mx0);
        const float mn1 = fmaxf(mi1, mx1);
        const float al0 = __expf(mi0 - mn0);
        const float al1 = __expf(mi1 - mn1);

        float sum0 = 0.f, sum1 = 0.f;
#pragma unroll
        for (int nf = 0; nf < 8; nf++) {
            float e;
            e = __expf(c[nf][0] - mn0); sum0 += e; c[nf][0] = e;
            e = __expf(c[nf][1] - mn0); sum0 += e; c[nf][1] = e;
            e = __expf(c[nf][2] - mn1); sum1 += e; c[nf][2] = e;
            e = __expf(c[nf][3] - mn1); sum1 += e; c[nf][3] = e;
        }
        sum0 += __shfl_xor_sync(0xffffffffu, sum0, 1);
        sum0 += __shfl_xor_sync(0xffffffffu, sum0, 2);
        sum1 += __shfl_xor_sync(0xffffffffu, sum1, 1);
        sum1 += __shfl_xor_sync(0xffffffffu, sum1, 2);

        li0 = li0 * al0 + sum0;  mi0 = mn0;
        li1 = li1 * al1 + sum1;  mi1 = mn1;

#pragma unroll
        for (int nf = 0; nf < 8; nf++) {
            o[nf][0] *= al0; o[nf][1] *= al0;
            o[nf][2] *= al1; o[nf][3] *= al1;
        }

        const int lmi = lane >> 3;
        const int lmr = lane & 7;
#pragma unroll
        for (int s = 0; s < 4; s++) {
            uint32_t a[4];
            a[0] = packh2(c[2 * s][0],     c[2 * s][1]);
            a[1] = packh2(c[2 * s][2],     c[2 * s][3]);
            a[2] = packh2(c[2 * s + 1][0], c[2 * s + 1][1]);
            a[3] = packh2(c[2 * s + 1][2], c[2 * s + 1][3]);
#pragma unroll
            for (int nfp = 0; nfp < 4; nfp++) {
                const int vrow = 16 * s + ((lmi & 1) << 3) + lmr;
                const int vcol = 16 * nfp + ((lmi >> 1) << 3);
                uint32_t b0, b1, b2, b3;
                ldsm_x4_t(b0, b1, b2, b3,
                          Vb2 + (uint32_t)vrow * VSTRB + (uint32_t)vcol * 2);
                { uint32_t bb[2] = { b0, b1 }; mma_f16(o[2 * nfp],     a, bb); }
                { uint32_t bb[2] = { b2, b3 }; mma_f16(o[2 * nfp + 1], a, bb); }
            }
        }
    }

    const float inv0 = 1.0f / li0;
    const float inv1 = 1.0f / li1;
    __half* row0g = O + (size_t)(b * S_ + q0 + qrow0) * D_ + (size_t)h * HD_;
    __half* row1g = row0g + (size_t)8 * D_;
#pragma unroll
    for (int nf = 0; nf < 8; nf++) {
        const int d0 = nf * 8 + 2 * qid;
        *(uint32_t*)(row0g + d0) = packh2(o[nf][0] * inv0, o[nf][1] * inv0);
        *(uint32_t*)(row1g + d0) = packh2(o[nf][2] * inv1, o[nf][3] * inv1);
    }
}

// ---------------------------------------------------------------------------
// Launch.  Inputs: x, Wq, bq, Wk, bk, Wv, bv, W1, b1, W2, b2, mask
// ---------------------------------------------------------------------------
extern "C" void kernel_launch(void* const* d_in, const int* in_sizes, int n_in,
                              void* d_out, int out_size)
{
    const float* x    = (const float*)d_in[0];
    const float* Wq   = (const float*)d_in[1];
    const float* bq   = (const float*)d_in[2];
    const float* Wk   = (const float*)d_in[3];
    const float* bk   = (const float*)d_in[4];
    const float* Wv   = (const float*)d_in[5];
    const float* bv   = (const float*)d_in[6];
    const float* W1   = (const float*)d_in[7];
    const float* b1   = (const float*)d_in[8];
    const float* W2   = (const float*)d_in[9];
    const float* b2   = (const float*)d_in[10];
    const int*   mask = (const int*)d_in[11];
    float*       out  = (float*)d_out;

    __half *Xh, *Wqkvh, *W1h, *W2h, *QKVh, *Chp, *Hhp;
    float *bqkvp;
    int *mflagp;
    cudaGetSymbolAddress((void**)&Xh,     g_Xh);
    cudaGetSymbolAddress((void**)&Wqkvh,  g_Wqkvh);
    cudaGetSymbolAddress((void**)&W1h,    g_W1h);
    cudaGetSymbolAddress((void**)&W2h,    g_W2h);
    cudaGetSymbolAddress((void**)&QKVh,   g_QKVh);
    cudaGetSymbolAddress((void**)&Chp,    g_Ch);
    cudaGetSymbolAddress((void**)&Hhp,    g_Hh);
    cudaGetSymbolAddress((void**)&bqkvp,  g_bqkv);
    cudaGetSymbolAddress((void**)&mflagp, g_mflag);

    cudaFuncSetAttribute(attn_h,
                         cudaFuncAttributeMaxDynamicSharedMemorySize, ATTN_SMEM_BYTES);
    cudaFuncSetAttribute((const void*)gemm_h<0>,
                         cudaFuncAttributeMaxDynamicSharedMemorySize, HGEMM_SMEM);
    cudaFuncSetAttribute((const void*)gemm_h<1>,
                         cudaFuncAttributeMaxDynamicSharedMemorySize, HGEMM_SMEM);
    cudaFuncSetAttribute((const void*)gemm_h<2>,
                         cudaFuncAttributeMaxDynamicSharedMemorySize, HGEMM_SMEM);

    const dim3 blk(256);
    const int T = 256;

    // ---- prep ----
    HSegs P;
    P.src[0] = x;  P.dst[0] = Xh;
    P.src[1] = Wq; P.dst[1] = Wqkvh;
    P.src[2] = Wk; P.dst[2] = Wqkvh + (size_t)D_ * D_;
    P.src[3] = Wv; P.dst[3] = Wqkvh + (size_t)2 * D_ * D_;
    P.src[4] = W1; P.dst[4] = W1h;
    P.src[5] = W2; P.dst[5] = W2h;
    const int gr[6] = { M_ * D_ / 16, D_ * D_ / 16, D_ * D_ / 16, D_ * D_ / 16,
                        2 * D_ * D_ / 16, 2 * D_ * D_ / 16 };
    P.cum[0] = 0;
    for (int j = 0; j < 6; j++) P.cum[j + 1] = P.cum[j] + gr[j];
    round_half_all<<<(P.cum[6] + T - 1) / T, T>>>(P);
    concat_bias<<<(3 * D_ + T - 1) / T, T>>>(bq, bk, bv, bqkvp);
    mask_scan<<<B_ * (S_ / 128) * (S_ / 64), T>>>(mask, mflagp);

    // ---- fused QKV projection ----
    gemm_h<0><<<dim3(3 * D_ / 128, M_ / 128), blk, HGEMM_SMEM>>>(
        Xh, Wqkvh, bqkvp, (float*)nullptr, QKVh, M_, 3 * D_, D_);

    // ---- attention ----
    attn_h<<<dim3(S_ / QT_, B_ * H_), blk, ATTN_SMEM_BYTES>>>(QKVh, mask, mflagp, Chp);

    // ---- MLP ----
    gemm_h<1><<<dim3(2 * D_ / 128, M_ / 128), blk, HGEMM_SMEM>>>(
        Chp, W1h, b1, (float*)nullptr, Hhp, M_, 2 * D_, D_);
    gemm_h<2><<<dim3(D_ / 128, M_ / 128), blk, HGEMM_SMEM>>>(
        Hhp, W2h, b2, out, (__half*)nullptr, M_, D_, 2 * D_);
}

// round 14
// speedup vs baseline: 1.6088x; 1.6088x over previous
#include <cuda_runtime.h>
#include <cuda_fp16.h>
#include <stdint.h>

#define B_  4
#define S_  1024
#define D_  1024
#define H_  16
#define HD_ 64
#define M_  (B_ * S_)     // 4096

// ---------------------------------------------------------------------------
// Scratch (device globals)
// ---------------------------------------------------------------------------
__device__ __align__(16) __half g_Xh   [(size_t)M_ * D_];
__device__ __align__(16) __half g_Wqkvh[(size_t)3 * D_ * D_];
__device__ __align__(16) __half g_W1h  [(size_t)2 * D_ * D_];
__device__ __align__(16) __half g_W2h  [(size_t)2 * D_ * D_];
__device__ __align__(16) __half g_QKVh [(size_t)M_ * 3 * D_];    // Q,K permuted; V plain
__device__ __align__(16) __half g_Ch   [(size_t)M_ * D_];
__device__ __align__(16) __half g_Hh   [(size_t)M_ * 2 * D_];
__device__ __align__(16) float  g_bqkv [3 * D_];
__device__ int g_mflag[B_ * (S_ / 128) * (S_ / 64)];

#define NSM_X2 304   // persistent grid: ~2 CTAs per SM on GB300 (152 SMs)

// ---------------------------------------------------------------------------
__device__ __forceinline__ void mma_f16(float* c, const uint32_t* a, const uint32_t* b) {
    asm volatile(
        "mma.sync.aligned.m16n8k16.row.col.f32.f16.f16.f32 "
        "{%0,%1,%2,%3}, {%4,%5,%6,%7}, {%8,%9}, {%0,%1,%2,%3};\n"
        : "+f"(c[0]), "+f"(c[1]), "+f"(c[2]), "+f"(c[3])
        : "r"(a[0]), "r"(a[1]), "r"(a[2]), "r"(a[3]), "r"(b[0]), "r"(b[1]));
}

__device__ __forceinline__ void ldsm_x4(uint32_t& r0, uint32_t& r1,
                                        uint32_t& r2, uint32_t& r3, uint32_t addr) {
    asm volatile("ldmatrix.sync.aligned.m8n8.x4.shared.b16 {%0,%1,%2,%3}, [%4];"
                 : "=r"(r0), "=r"(r1), "=r"(r2), "=r"(r3) : "r"(addr));
}

__device__ __forceinline__ void ldsm_x4_t(uint32_t& r0, uint32_t& r1,
                                          uint32_t& r2, uint32_t& r3, uint32_t addr) {
    asm volatile("ldmatrix.sync.aligned.m8n8.x4.trans.shared.b16 {%0,%1,%2,%3}, [%4];"
                 : "=r"(r0), "=r"(r1), "=r"(r2), "=r"(r3) : "r"(addr));
}

__device__ __forceinline__ uint32_t smem_u32(const void* p) {
    uint32_t a;
    asm("{ .reg .u64 t; cvta.to.shared.u64 t, %1; cvt.u32.u64 %0, t; }"
        : "=r"(a) : "l"(p));
    return a;
}

__device__ __forceinline__ void cp_async16(uint32_t dst, const void* src) {
    asm volatile("cp.async.cg.shared.global [%0], [%1], 16;"
                 :: "r"(dst), "l"(src) : "memory");
}

__device__ __forceinline__ uint32_t packh2(float x, float y) {
    __half2 h = __floats2half2_rn(x, y);
    return *(uint32_t*)&h;
}

__device__ __forceinline__ int permn(int n0) {
    return (n0 & ~15) | (((n0 >> 1) & 3) << 2) | ((n0 & 8) >> 2);
}

// ---------------------------------------------------------------------------
// Prep kernels
// ---------------------------------------------------------------------------
struct HSegs {
    const float* src[6];
    __half*      dst[6];
    int          cum[7];
};

__global__ void round_half_all(HSegs P) {
    const int i = blockIdx.x * blockDim.x + threadIdx.x;
    if (i >= P.cum[6]) return;
#pragma unroll
    for (int j = 0; j < 6; j++) {
        if (i < P.cum[j + 1]) {
            const int g = i - P.cum[j];
            const float4* s = (const float4*)P.src[j] + (size_t)g * 4;
            float l[16];
            *(float4*)&l[0]  = s[0];
            *(float4*)&l[4]  = s[1];
            *(float4*)&l[8]  = s[2];
            *(float4*)&l[12] = s[3];
            uint4 o0, o1;
            o0.x = packh2(l[0],  l[1]);  o0.y = packh2(l[2],  l[3]);
            o0.z = packh2(l[4],  l[5]);  o0.w = packh2(l[6],  l[7]);
            o1.x = packh2(l[8],  l[9]);  o1.y = packh2(l[10], l[11]);
            o1.z = packh2(l[12], l[13]); o1.w = packh2(l[14], l[15]);
            uint4* d = (uint4*)(P.dst[j] + (size_t)g * 16);
            d[0] = o0; d[1] = o1;
            return;
        }
    }
}

__global__ void concat_bias(const float* __restrict__ a, const float* __restrict__ b,
                            const float* __restrict__ c, float* __restrict__ dst) {
    const int i = blockIdx.x * blockDim.x + threadIdx.x;
    if (i < 3 * D_)
        dst[i] = (i < D_) ? a[i] : ((i < 2 * D_) ? b[i - D_] : c[i - 2 * D_]);
}

__global__ __launch_bounds__(256)
void mask_scan(const int* __restrict__ mask, int* __restrict__ flags) {
    const int fidx = blockIdx.x;
    const int kt = fidx & 15;
    const int qt = (fidx >> 4) & 7;
    const int b  = fidx >> 7;
    const int q0 = qt * 128;
    const int k0 = kt * 64;
    const int tid = threadIdx.x;

    int ok = 1;
#pragma unroll
    for (int i = 0; i < 8; i++) {
        const int idx = tid + 256 * i;
        const int row = idx >> 4;
        const int c4  = (idx & 15) * 4;
        const int4 v = *(const int4*)&mask[((size_t)(b * S_ + q0 + row)) * S_ + k0 + c4];
        if (v.x == 0 || v.y == 0 || v.z == 0 || v.w == 0) ok = 0;
    }
    const int all_ok = __syncthreads_and(ok);
    if (tid == 0) flags[fidx] = !all_ok;
}

// ---------------------------------------------------------------------------
// fp16 tensor-core GEMM: 128x128 tile, K-stage 64, 3-stage cp.async,
// XOR-swizzled smem + ldmatrix, PERSISTENT CTAs (tile loop).
// MODE: 0 = QKV (fp16 out: Q prescale+permute, K permute, V plain),
//       1 = MLP1 (ReLU, standard fp16 out), 2 = MLP2 (fp32 out).
// ---------------------------------------------------------------------------
#define GROWB 128
#define GSTG_B (128 * GROWB)           // 16,384 per matrix per stage
#define GSTAGE_B (2 * GSTG_B)          // 32,768
#define GNST 3
#define HGEMM_SMEM (GNST * GSTAGE_B)   // 98,304

template <int MODE>
__global__ __launch_bounds__(256, 2)
void gemm_h(const __half* __restrict__ A, const __half* __restrict__ Bm,
            const float* __restrict__ bias, float* __restrict__ Cf,
            __half* __restrict__ Ch, int M, int N, int K)
{
    extern __shared__ __align__(16) char smc[];
    const uint32_t sb = smem_u32(smc);

    const int tid  = threadIdx.x;
    const int lane = tid & 31;
    const int wid  = tid >> 5;
    const int wm   = wid >> 2;
    const int wn   = wid & 3;
    const int grp  = lane >> 2;
    const int qid  = lane & 3;

    const int NT_N = N >> 7;
    const int NT   = (M >> 7) * NT_N;
    const int KT   = K / 64;

    // ldmatrix lane-address components (constant per thread)
    const int al8 = (lane & 7) + ((lane >> 3) & 1) * 8;
    const int ach = lane >> 4;
    const int bl8 = lane & 7;
    const int bg  = lane >> 3;

    for (int t = blockIdx.x; t < NT; t += gridDim.x) {
        const int bm = (t / NT_N) * 128;
        const int bn = (t % NT_N) * 128;

        const __half* AgBase = A  + (size_t)bm * K;
        const __half* BgBase = Bm + (size_t)bn * K;

        auto issue_stage = [&](int stage, int buf) {
            const int k0 = stage * 64;
            const uint32_t sA = sb + (uint32_t)buf * GSTAGE_B;
            const uint32_t sB = sA + GSTG_B;
#pragma unroll
            for (int i = 0; i < 4; i++) {
                const int ci  = tid + 256 * i;
                const int row = ci >> 3;
                const int c   = ci & 7;
                cp_async16(sA + (uint32_t)row * GROWB + (uint32_t)((c ^ (row & 7)) << 4),
                           AgBase + (size_t)row * K + k0 + c * 8);
            }
#pragma unroll
            for (int i = 0; i < 4; i++) {
                const int ci  = tid + 256 * i;
                const int row = ci >> 3;
                const int c   = ci & 7;
                cp_async16(sB + (uint32_t)row * GROWB + (uint32_t)((c ^ (row & 7)) << 4),
                           BgBase + (size_t)row * K + k0 + c * 8);
            }
            asm volatile("cp.async.commit_group;" ::: "memory");
        };

        float acc[4][4][4];
#pragma unroll
        for (int i = 0; i < 4; i++)
#pragma unroll
            for (int j = 0; j < 4; j++)
#pragma unroll
                for (int r = 0; r < 4; r++) acc[i][j][r] = 0.f;

        issue_stage(0, 0);
        issue_stage(1, 1);

        for (int kt = 0; kt < KT; kt++) {
            const int buf = kt % GNST;

            if (kt < KT - 1)
                asm volatile("cp.async.wait_group 1;" ::: "memory");
            else
                asm volatile("cp.async.wait_group 0;" ::: "memory");
            __syncthreads();

            if (kt + 2 < KT)
                issue_stage(kt + 2, (kt + 2) % GNST);

            const uint32_t sA = sb + (uint32_t)buf * GSTAGE_B;
            const uint32_t sB = sA + GSTG_B;

#pragma unroll
            for (int s = 0; s < 4; s++) {
                uint32_t a[4][4];
#pragma unroll
                for (int mf = 0; mf < 4; mf++) {
                    const int arow = wm * 64 + mf * 16 + al8;
                    const int c    = (s * 2 + ach) ^ (arow & 7);
                    ldsm_x4(a[mf][0], a[mf][1], a[mf][2], a[mf][3],
                            sA + (uint32_t)arow * GROWB + (uint32_t)(c << 4));
                }
                uint32_t b[4][2];
#pragma unroll
                for (int nfp = 0; nfp < 2; nfp++) {
                    const int brow = wn * 32 + nfp * 16 + (bg >> 1) * 8 + bl8;
                    const int c    = (s * 2 + (bg & 1)) ^ (brow & 7);
                    ldsm_x4(b[2 * nfp][0], b[2 * nfp][1],
                            b[2 * nfp + 1][0], b[2 * nfp + 1][1],
                            sB + (uint32_t)brow * GROWB + (uint32_t)(c << 4));
                }
#pragma unroll
                for (int mf = 0; mf < 4; mf++)
#pragma unroll
                    for (int nf = 0; nf < 4; nf++)
                        mma_f16(acc[mf][nf], a[mf], b[nf]);
            }
        }

        // ---- Epilogue ----
#pragma unroll
        for (int mf = 0; mf < 4; mf++) {
#pragma unroll
            for (int nf = 0; nf < 4; nf++) {
                const int m0 = bm + wm * 64 + mf * 16 + grp;
                const int n0 = bn + wn * 32 + nf * 8 + 2 * qid;
                const float bx = bias[n0], by = bias[n0 + 1];
                float2 v0, v1;
                v0.x = acc[mf][nf][0] + bx; v0.y = acc[mf][nf][1] + by;
                v1.x = acc[mf][nf][2] + bx; v1.y = acc[mf][nf][3] + by;

                if (MODE == 0) {
                    if (n0 < D_) {
                        v0.x *= 0.125f; v0.y *= 0.125f;
                        v1.x *= 0.125f; v1.y *= 0.125f;
                    }
                    const int pn = (n0 < 2 * D_) ? permn(n0) : n0;
                    *(uint32_t*)&Ch[(size_t)m0 * N + pn]       = packh2(v0.x, v0.y);
                    *(uint32_t*)&Ch[(size_t)(m0 + 8) * N + pn] = packh2(v1.x, v1.y);
                } else if (MODE == 1) {
                    v0.x = fmaxf(v0.x, 0.f); v0.y = fmaxf(v0.y, 0.f);
                    v1.x = fmaxf(v1.x, 0.f); v1.y = fmaxf(v1.y, 0.f);
                    *(uint32_t*)&Ch[(size_t)m0 * N + n0]       = packh2(v0.x, v0.y);
                    *(uint32_t*)&Ch[(size_t)(m0 + 8) * N + n0] = packh2(v1.x, v1.y);
                } else {
                    *(float2*)&Cf[(size_t)m0 * N + n0]       = v0;
                    *(float2*)&Cf[(size_t)(m0 + 8) * N + n0] = v1;
                }
            }
        }

        // all warps done reading smem before next tile's loads overwrite it
        __syncthreads();
    }
}

// ---------------------------------------------------------------------------
// fp16 tensor-core flash attention (R12 exact: 2 CTAs/SM).
// ---------------------------------------------------------------------------
#define QT_ 128
#define QSTRB 160
#define KSTRB 160
#define VSTRB 144
#define QS_BYTES   (QT_ * QSTRB)
#define KSTG_BYTES (64 * KSTRB)
#define VSTG_BYTES (64 * VSTRB)
#define ATTN_SMEM_BYTES (QS_BYTES + 2 * KSTG_BYTES + 2 * VSTG_BYTES)  // 59,392

__global__ __launch_bounds__(256, 2)
void attn_h(const __half* __restrict__ QKV, const int* __restrict__ mask,
            const int* __restrict__ mflag, __half* __restrict__ O)
{
    extern __shared__ __align__(16) char smb[];
    const uint32_t sb  = smem_u32(smb);
    const uint32_t sQ  = sb;
    const uint32_t sK  = sb + QS_BYTES;
    const uint32_t sV  = sK + 2 * KSTG_BYTES;
    const char* Qsp = smb;
    const char* Ksp = smb + QS_BYTES;

    const int tid  = threadIdx.x;
    const int lane = tid & 31;
    const int wid  = tid >> 5;
    const int grp  = lane >> 2;
    const int qid  = lane & 3;

    const int qt = blockIdx.x;
    const int bh = blockIdx.y;
    const int b  = bh >> 4;
    const int h  = bh & 15;
    const int q0 = qt * QT_;

    const int LDQ = 3 * D_;
    const __half* Qb = QKV + (size_t)b * S_ * LDQ + (size_t)h * HD_;
    const __half* Kb = Qb + D_;
    const __half* Vb = Qb + 2 * D_;
    const int* mfbase = mflag + (b * (S_ / QT_) + qt) * (S_ / 64);

    auto issue_kv = [&](int kt, int buf) {
        const int k0g = kt * 64;
#pragma unroll
        for (int i = 0; i < 2; i++) {
            const int idx = tid + 256 * i;
            const int row = idx >> 3;
            const int ch  = idx & 7;
            cp_async16(sK + (uint32_t)buf * KSTG_BYTES + (uint32_t)row * KSTRB + ch * 16,
                       Kb + (size_t)(k0g + row) * LDQ + ch * 8);
            cp_async16(sV + (uint32_t)buf * VSTG_BYTES + (uint32_t)row * VSTRB + ch * 16,
                       Vb + (size_t)(k0g + row) * LDQ + ch * 8);
        }
        asm volatile("cp.async.commit_group;" ::: "memory");
    };

    issue_kv(0, 0);

#pragma unroll
    for (int i = 0; i < 4; i++) {
        const int idx = tid + 256 * i;
        const int row = idx >> 3;
        const int ch  = idx & 7;
        cp_async16(sQ + (uint32_t)row * QSTRB + ch * 16,
                   Qb + (size_t)(q0 + row) * LDQ + ch * 8);
    }
    asm volatile("cp.async.commit_group;" ::: "memory");

    const int qrow0 = wid * 16 + grp;
    const int* mrow0 = mask + (size_t)(b * S_ + q0 + qrow0) * S_;
    const int* mrow1 = mrow0 + 8 * S_;

    float mi0 = -1e30f, mi1 = -1e30f, li0 = 0.f, li1 = 0.f;
    float o[8][4];
#pragma unroll
    for (int nf = 0; nf < 8; nf++)
#pragma unroll
        for (int r = 0; r < 4; r++) o[nf][r] = 0.f;

    for (int kt = 0; kt < S_ / 64; kt++) {
        const int buf = kt & 1;
        const int k0  = kt * 64;
        const bool dirty = mfbase[kt] != 0;

        asm volatile("cp.async.wait_group 0;" ::: "memory");
        __syncthreads();

        if (kt + 1 < S_ / 64)
            issue_kv(kt + 1, buf ^ 1);

        const char* Kb2 = Ksp + (size_t)buf * KSTG_BYTES;
        const uint32_t Vb2 = sV + (uint32_t)buf * VSTG_BYTES;

        float c[8][4];
#pragma unroll
        for (int nf = 0; nf < 8; nf++)
#pragma unroll
            for (int r = 0; r < 4; r++) c[nf][r] = 0.f;

#pragma unroll
        for (int s = 0; s < 4; s++) {
            const uint2 lo = *(const uint2*)(Qsp + qrow0 * QSTRB + s * 32 + qid * 8);
            const uint2 hi = *(const uint2*)(Qsp + (qrow0 + 8) * QSTRB + s * 32 + qid * 8);
            uint32_t a[4] = { lo.x, hi.x, lo.y, hi.y };
#pragma unroll
            for (int nf = 0; nf < 8; nf++) {
                const uint2 bv = *(const uint2*)(Kb2 + (nf * 8 + grp) * KSTRB + s * 32 + qid * 8);
                uint32_t bb[2] = { bv.x, bv.y };
                mma_f16(c[nf], a, bb);
            }
        }

        if (dirty) {
#pragma unroll
            for (int nf = 0; nf < 8; nf++) {
                const int kc = k0 + nf * 8 + 2 * qid;
                const int2 m0 = *(const int2*)&mrow0[kc];
                const int2 m1 = *(const int2*)&mrow1[kc];
                if (m0.x == 0) c[nf][0] = -1e8f;
                if (m0.y == 0) c[nf][1] = -1e8f;
                if (m1.x == 0) c[nf][2] = -1e8f;
                if (m1.y == 0) c[nf][3] = -1e8f;
            }
        }

        float mx0 = -1e30f, mx1 = -1e30f;
#pragma unroll
        for (int nf = 0; nf < 8; nf++) {
            mx0 = fmaxf(mx0, fmaxf(c[nf][0], c[nf][1]));
            mx1 = fmaxf(mx1, fmaxf(c[nf][2], c[nf][3]));
        }
        mx0 = fmaxf(mx0, __shfl_xor_sync(0xffffffffu, mx0, 1));
        mx0 = fmaxf(mx0, __shfl_xor_sync(0xffffffffu, mx0, 2));
        mx1 = fmaxf(mx1, __shfl_xor_sync(0xffffffffu, mx1, 1));
        mx1 = fmaxf(mx1, __shfl_xor_sync(0xffffffffu, mx1, 2));

        const float mn0 = fmaxf(mi0, mx0);
        const float mn1 = fmaxf(mi1, mx1);
        const float al0 = __expf(mi0 - mn0);
        const float al1 = __expf(mi1 - mn1);

        float sum0 = 0.f, sum1 = 0.f;
#pragma unroll
        for (int nf = 0; nf < 8; nf++) {
            float e;
            e = __expf(c[nf][0] - mn0); sum0 += e; c[nf][0] = e;
            e = __expf(c[nf][1] - mn0); sum0 += e; c[nf][1] = e;
            e = __expf(c[nf][2] - mn1); sum1 += e; c[nf][2] = e;
            e = __expf(c[nf][3] - mn1); sum1 += e; c[nf][3] = e;
        }
        sum0 += __shfl_xor_sync(0xffffffffu, sum0, 1);
        sum0 += __shfl_xor_sync(0xffffffffu, sum0, 2);
        sum1 += __shfl_xor_sync(0xffffffffu, sum1, 1);
        sum1 += __shfl_xor_sync(0xffffffffu, sum1, 2);

        li0 = li0 * al0 + sum0;  mi0 = mn0;
        li1 = li1 * al1 + sum1;  mi1 = mn1;

#pragma unroll
        for (int nf = 0; nf < 8; nf++) {
            o[nf][0] *= al0; o[nf][1] *= al0;
            o[nf][2] *= al1; o[nf][3] *= al1;
        }

        const int lmi = lane >> 3;
        const int lmr = lane & 7;
#pragma unroll
        for (int s = 0; s < 4; s++) {
            uint32_t a[4];
            a[0] = packh2(c[2 * s][0],     c[2 * s][1]);
            a[1] = packh2(c[2 * s][2],     c[2 * s][3]);
            a[2] = packh2(c[2 * s + 1][0], c[2 * s + 1][1]);
            a[3] = packh2(c[2 * s + 1][2], c[2 * s + 1][3]);
#pragma unroll
            for (int nfp = 0; nfp < 4; nfp++) {
                const int vrow = 16 * s + ((lmi & 1) << 3) + lmr;
                const int vcol = 16 * nfp + ((lmi >> 1) << 3);
                uint32_t b0, b1, b2, b3;
                ldsm_x4_t(b0, b1, b2, b3,
                          Vb2 + (uint32_t)vrow * VSTRB + (uint32_t)vcol * 2);
                { uint32_t bb[2] = { b0, b1 }; mma_f16(o[2 * nfp],     a, bb); }
                { uint32_t bb[2] = { b2, b3 }; mma_f16(o[2 * nfp + 1], a, bb); }
            }
        }
    }

    const float inv0 = 1.0f / li0;
    const float inv1 = 1.0f / li1;
    __half* row0g = O + (size_t)(b * S_ + q0 + qrow0) * D_ + (size_t)h * HD_;
    __half* row1g = row0g + (size_t)8 * D_;
#pragma unroll
    for (int nf = 0; nf < 8; nf++) {
        const int d0 = nf * 8 + 2 * qid;
        *(uint32_t*)(row0g + d0) = packh2(o[nf][0] * inv0, o[nf][1] * inv0);
        *(uint32_t*)(row1g + d0) = packh2(o[nf][2] * inv1, o[nf][3] * inv1);
    }
}

// ---------------------------------------------------------------------------
// Launch.  Inputs: x, Wq, bq, Wk, bk, Wv, bv, W1, b1, W2, b2, mask
// ---------------------------------------------------------------------------
extern "C" void kernel_launch(void* const* d_in, const int* in_sizes, int n_in,
                              void* d_out, int out_size)
{
    const float* x    = (const float*)d_in[0];
    const float* Wq   = (const float*)d_in[1];
    const float* bq   = (const float*)d_in[2];
    const float* Wk   = (const float*)d_in[3];
    const float* bk   = (const float*)d_in[4];
    const float* Wv   = (const float*)d_in[5];
    const float* bv   = (const float*)d_in[6];
    const float* W1   = (const float*)d_in[7];
    const float* b1   = (const float*)d_in[8];
    const float* W2   = (const float*)d_in[9];
    const float* b2   = (const float*)d_in[10];
    const int*   mask = (const int*)d_in[11];
    float*       out  = (float*)d_out;

    __half *Xh, *Wqkvh, *W1h, *W2h, *QKVh, *Chp, *Hhp;
    float *bqkvp;
    int *mflagp;
    cudaGetSymbolAddress((void**)&Xh,     g_Xh);
    cudaGetSymbolAddress((void**)&Wqkvh,  g_Wqkvh);
    cudaGetSymbolAddress((void**)&W1h,    g_W1h);
    cudaGetSymbolAddress((void**)&W2h,    g_W2h);
    cudaGetSymbolAddress((void**)&QKVh,   g_QKVh);
    cudaGetSymbolAddress((void**)&Chp,    g_Ch);
    cudaGetSymbolAddress((void**)&Hhp,    g_Hh);
    cudaGetSymbolAddress((void**)&bqkvp,  g_bqkv);
    cudaGetSymbolAddress((void**)&mflagp, g_mflag);

    cudaFuncSetAttribute(attn_h,
                         cudaFuncAttributeMaxDynamicSharedMemorySize, ATTN_SMEM_BYTES);
    cudaFuncSetAttribute((const void*)gemm_h<0>,
                         cudaFuncAttributeMaxDynamicSharedMemorySize, HGEMM_SMEM);
    cudaFuncSetAttribute((const void*)gemm_h<1>,
                         cudaFuncAttributeMaxDynamicSharedMemorySize, HGEMM_SMEM);
    cudaFuncSetAttribute((const void*)gemm_h<2>,
                         cudaFuncAttributeMaxDynamicSharedMemorySize, HGEMM_SMEM);

    const dim3 blk(256);
    const int T = 256;

    // ---- prep ----
    HSegs P;
    P.src[0] = x;  P.dst[0] = Xh;
    P.src[1] = Wq; P.dst[1] = Wqkvh;
    P.src[2] = Wk; P.dst[2] = Wqkvh + (size_t)D_ * D_;
    P.src[3] = Wv; P.dst[3] = Wqkvh + (size_t)2 * D_ * D_;
    P.src[4] = W1; P.dst[4] = W1h;
    P.src[5] = W2; P.dst[5] = W2h;
    const int gr[6] = { M_ * D_ / 16, D_ * D_ / 16, D_ * D_ / 16, D_ * D_ / 16,
                        2 * D_ * D_ / 16, 2 * D_ * D_ / 16 };
    P.cum[0] = 0;
    for (int j = 0; j < 6; j++) P.cum[j + 1] = P.cum[j] + gr[j];
    round_half_all<<<(P.cum[6] + T - 1) / T, T>>>(P);
    concat_bias<<<(3 * D_ + T - 1) / T, T>>>(bq, bk, bv, bqkvp);
    mask_scan<<<B_ * (S_ / 128) * (S_ / 64), T>>>(mask, mflagp);

    // ---- fused QKV projection (persistent grid) ----
    {
        const int nt = (M_ / 128) * (3 * D_ / 128);
        gemm_h<0><<<(nt < NSM_X2 ? nt : NSM_X2), blk, HGEMM_SMEM>>>(
            Xh, Wqkvh, bqkvp, (float*)nullptr, QKVh, M_, 3 * D_, D_);
    }

    // ---- attention ----
    attn_h<<<dim3(S_ / QT_, B_ * H_), blk, ATTN_SMEM_BYTES>>>(QKVh, mask, mflagp, Chp);

    // ---- MLP (persistent grids) ----
    {
        const int nt1 = (M_ / 128) * (2 * D_ / 128);
        gemm_h<1><<<(nt1 < NSM_X2 ? nt1 : NSM_X2), blk, HGEMM_SMEM>>>(
            Chp, W1h, b1, (float*)nullptr, Hhp, M_, 2 * D_, D_);
        const int nt2 = (M_ / 128) * (D_ / 128);
        gemm_h<2><<<(nt2 < NSM_X2 ? nt2 : NSM_X2), blk, HGEMM_SMEM>>>(
            Hhp, W2h, b2, out, (__half*)nullptr, M_, D_, 2 * D_);
    }
}

// round 15
// speedup vs baseline: 1.6554x; 1.0290x over previous
#include <cuda_runtime.h>
#include <cuda_fp16.h>
#include <stdint.h>

#define B_  4
#define S_  1024
#define D_  1024
#define H_  16
#define HD_ 64
#define M_  (B_ * S_)     // 4096

// ---------------------------------------------------------------------------
// Scratch (device globals)
// ---------------------------------------------------------------------------
__device__ __align__(16) __half g_Xh   [(size_t)M_ * D_];
__device__ __align__(16) __half g_Wqkvh[(size_t)3 * D_ * D_];
__device__ __align__(16) __half g_W1h  [(size_t)2 * D_ * D_];
__device__ __align__(16) __half g_W2h  [(size_t)2 * D_ * D_];
__device__ __align__(16) __half g_QKVh [(size_t)M_ * 3 * D_];    // Q,K permuted; V plain
__device__ __align__(16) __half g_Ch   [(size_t)M_ * D_];
__device__ __align__(16) __half g_Hh   [(size_t)M_ * 2 * D_];
__device__ __align__(16) float  g_bqkv [3 * D_];
__device__ int g_mflag[B_ * (S_ / 128) * (S_ / 64)];

// ---------------------------------------------------------------------------
__device__ __forceinline__ void mma_f16(float* c, const uint32_t* a, const uint32_t* b) {
    asm volatile(
        "mma.sync.aligned.m16n8k16.row.col.f32.f16.f16.f32 "
        "{%0,%1,%2,%3}, {%4,%5,%6,%7}, {%8,%9}, {%0,%1,%2,%3};\n"
        : "+f"(c[0]), "+f"(c[1]), "+f"(c[2]), "+f"(c[3])
        : "r"(a[0]), "r"(a[1]), "r"(a[2]), "r"(a[3]), "r"(b[0]), "r"(b[1]));
}

__device__ __forceinline__ void ldsm_x4(uint32_t& r0, uint32_t& r1,
                                        uint32_t& r2, uint32_t& r3, uint32_t addr) {
    asm volatile("ldmatrix.sync.aligned.m8n8.x4.shared.b16 {%0,%1,%2,%3}, [%4];"
                 : "=r"(r0), "=r"(r1), "=r"(r2), "=r"(r3) : "r"(addr));
}

__device__ __forceinline__ void ldsm_x4_t(uint32_t& r0, uint32_t& r1,
                                          uint32_t& r2, uint32_t& r3, uint32_t addr) {
    asm volatile("ldmatrix.sync.aligned.m8n8.x4.trans.shared.b16 {%0,%1,%2,%3}, [%4];"
                 : "=r"(r0), "=r"(r1), "=r"(r2), "=r"(r3) : "r"(addr));
}

__device__ __forceinline__ uint32_t smem_u32(const void* p) {
    uint32_t a;
    asm("{ .reg .u64 t; cvta.to.shared.u64 t, %1; cvt.u32.u64 %0, t; }"
        : "=r"(a) : "l"(p));
    return a;
}

__device__ __forceinline__ void cp_async16(uint32_t dst, const void* src) {
    asm volatile("cp.async.cg.shared.global [%0], [%1], 16;"
                 :: "r"(dst), "l"(src) : "memory");
}

__device__ __forceinline__ uint32_t packh2(float x, float y) {
    __half2 h = __floats2half2_rn(x, y);
    return *(uint32_t*)&h;
}

__device__ __forceinline__ int permn(int n0) {
    return (n0 & ~15) | (((n0 >> 1) & 3) << 2) | ((n0 & 8) >> 2);
}

// ---------------------------------------------------------------------------
// Prep kernels
// ---------------------------------------------------------------------------
struct HSegs {
    const float* src[6];
    __half*      dst[6];
    int          cum[7];
};

__global__ void round_half_all(HSegs P) {
    const int i = blockIdx.x * blockDim.x + threadIdx.x;
    if (i >= P.cum[6]) return;
#pragma unroll
    for (int j = 0; j < 6; j++) {
        if (i < P.cum[j + 1]) {
            const int g = i - P.cum[j];
            const float4* s = (const float4*)P.src[j] + (size_t)g * 4;
            float l[16];
            *(float4*)&l[0]  = s[0];
            *(float4*)&l[4]  = s[1];
            *(float4*)&l[8]  = s[2];
            *(float4*)&l[12] = s[3];
            uint4 o0, o1;
            o0.x = packh2(l[0],  l[1]);  o0.y = packh2(l[2],  l[3]);
            o0.z = packh2(l[4],  l[5]);  o0.w = packh2(l[6],  l[7]);
            o1.x = packh2(l[8],  l[9]);  o1.y = packh2(l[10], l[11]);
            o1.z = packh2(l[12], l[13]); o1.w = packh2(l[14], l[15]);
            uint4* d = (uint4*)(P.dst[j] + (size_t)g * 16);
            d[0] = o0; d[1] = o1;
            return;
        }
    }
}

__global__ void concat_bias(const float* __restrict__ a, const float* __restrict__ b,
                            const float* __restrict__ c, float* __restrict__ dst) {
    const int i = blockIdx.x * blockDim.x + threadIdx.x;
    if (i < 3 * D_)
        dst[i] = (i < D_) ? a[i] : ((i < 2 * D_) ? b[i - D_] : c[i - 2 * D_]);
}

__global__ __launch_bounds__(256)
void mask_scan(const int* __restrict__ mask, int* __restrict__ flags) {
    const int fidx = blockIdx.x;
    const int kt = fidx & 15;
    const int qt = (fidx >> 4) & 7;
    const int b  = fidx >> 7;
    const int q0 = qt * 128;
    const int k0 = kt * 64;
    const int tid = threadIdx.x;

    int ok = 1;
#pragma unroll
    for (int i = 0; i < 8; i++) {
        const int idx = tid + 256 * i;
        const int row = idx >> 4;
        const int c4  = (idx & 15) * 4;
        const int4 v = *(const int4*)&mask[((size_t)(b * S_ + q0 + row)) * S_ + k0 + c4];
        if (v.x == 0 || v.y == 0 || v.z == 0 || v.w == 0) ok = 0;
    }
    const int all_ok = __syncthreads_and(ok);
    if (tid == 0) flags[fidx] = !all_ok;
}

// ---------------------------------------------------------------------------
// fp16 tensor-core GEMM (R12 exact): 128x128 tile, K-stage 64, 3-stage
// cp.async, XOR-swizzled smem + ldmatrix fragment loads, 2 CTAs/SM.
// ---------------------------------------------------------------------------
#define GROWB 128
#define GSTG_B (128 * GROWB)
#define GSTAGE_B (2 * GSTG_B)
#define GNST 3
#define HGEMM_SMEM (GNST * GSTAGE_B)   // 98,304

template <int MODE>
__global__ __launch_bounds__(256, 2)
void gemm_h(const __half* __restrict__ A, const __half* __restrict__ Bm,
            const float* __restrict__ bias, float* __restrict__ Cf,
            __half* __restrict__ Ch, int M, int N, int K)
{
    extern __shared__ __align__(16) char smc[];
    const uint32_t sb = smem_u32(smc);

    const int tid  = threadIdx.x;
    const int lane = tid & 31;
    const int wid  = tid >> 5;
    const int wm   = wid >> 2;
    const int wn   = wid & 3;
    const int grp  = lane >> 2;
    const int qid  = lane & 3;

    const int bm = blockIdx.y * 128;
    const int bn = blockIdx.x * 128;

    const __half* AgBase = A  + (size_t)bm * K;
    const __half* BgBase = Bm + (size_t)bn * K;

    auto issue_stage = [&](int stage, int buf) {
        const int k0 = stage * 64;
        const uint32_t sA = sb + (uint32_t)buf * GSTAGE_B;
        const uint32_t sB = sA + GSTG_B;
#pragma unroll
        for (int i = 0; i < 4; i++) {
            const int ci  = tid + 256 * i;
            const int row = ci >> 3;
            const int c   = ci & 7;
            cp_async16(sA + (uint32_t)row * GROWB + (uint32_t)((c ^ (row & 7)) << 4),
                       AgBase + (size_t)row * K + k0 + c * 8);
        }
#pragma unroll
        for (int i = 0; i < 4; i++) {
            const int ci  = tid + 256 * i;
            const int row = ci >> 3;
            const int c   = ci & 7;
            cp_async16(sB + (uint32_t)row * GROWB + (uint32_t)((c ^ (row & 7)) << 4),
                       BgBase + (size_t)row * K + k0 + c * 8);
        }
        asm volatile("cp.async.commit_group;" ::: "memory");
    };

    float acc[4][4][4];
#pragma unroll
    for (int i = 0; i < 4; i++)
#pragma unroll
        for (int j = 0; j < 4; j++)
#pragma unroll
            for (int r = 0; r < 4; r++) acc[i][j][r] = 0.f;

    const int KT = K / 64;

    issue_stage(0, 0);
    issue_stage(1, 1);

    const int al8 = (lane & 7) + ((lane >> 3) & 1) * 8;
    const int ach = lane >> 4;
    const int bl8 = lane & 7;
    const int bg  = lane >> 3;

    for (int kt = 0; kt < KT; kt++) {
        const int buf = kt % GNST;

        if (kt < KT - 1)
            asm volatile("cp.async.wait_group 1;" ::: "memory");
        else
            asm volatile("cp.async.wait_group 0;" ::: "memory");
        __syncthreads();

        if (kt + 2 < KT)
            issue_stage(kt + 2, (kt + 2) % GNST);

        const uint32_t sA = sb + (uint32_t)buf * GSTAGE_B;
        const uint32_t sB = sA + GSTG_B;

#pragma unroll
        for (int s = 0; s < 4; s++) {
            uint32_t a[4][4];
#pragma unroll
            for (int mf = 0; mf < 4; mf++) {
                const int arow = wm * 64 + mf * 16 + al8;
                const int c    = (s * 2 + ach) ^ (arow & 7);
                ldsm_x4(a[mf][0], a[mf][1], a[mf][2], a[mf][3],
                        sA + (uint32_t)arow * GROWB + (uint32_t)(c << 4));
            }
            uint32_t b[4][2];
#pragma unroll
            for (int nfp = 0; nfp < 2; nfp++) {
                const int brow = wn * 32 + nfp * 16 + (bg >> 1) * 8 + bl8;
                const int c    = (s * 2 + (bg & 1)) ^ (brow & 7);
                ldsm_x4(b[2 * nfp][0], b[2 * nfp][1], b[2 * nfp + 1][0], b[2 * nfp + 1][1],
                        sB + (uint32_t)brow * GROWB + (uint32_t)(c << 4));
            }
#pragma unroll
            for (int mf = 0; mf < 4; mf++)
#pragma unroll
                for (int nf = 0; nf < 4; nf++)
                    mma_f16(acc[mf][nf], a[mf], b[nf]);
        }
    }

    // ---- Epilogue ----
#pragma unroll
    for (int mf = 0; mf < 4; mf++) {
#pragma unroll
        for (int nf = 0; nf < 4; nf++) {
            const int m0 = bm + wm * 64 + mf * 16 + grp;
            const int n0 = bn + wn * 32 + nf * 8 + 2 * qid;
            const float bx = bias[n0], by = bias[n0 + 1];
            float2 v0, v1;
            v0.x = acc[mf][nf][0] + bx; v0.y = acc[mf][nf][1] + by;
            v1.x = acc[mf][nf][2] + bx; v1.y = acc[mf][nf][3] + by;

            if (MODE == 0) {
                if (n0 < D_) {
                    v0.x *= 0.125f; v0.y *= 0.125f;
                    v1.x *= 0.125f; v1.y *= 0.125f;
                }
                const int pn = (n0 < 2 * D_) ? permn(n0) : n0;
                *(uint32_t*)&Ch[(size_t)m0 * N + pn]       = packh2(v0.x, v0.y);
                *(uint32_t*)&Ch[(size_t)(m0 + 8) * N + pn] = packh2(v1.x, v1.y);
            } else if (MODE == 1) {
                v0.x = fmaxf(v0.x, 0.f); v0.y = fmaxf(v0.y, 0.f);
                v1.x = fmaxf(v1.x, 0.f); v1.y = fmaxf(v1.y, 0.f);
                *(uint32_t*)&Ch[(size_t)m0 * N + n0]       = packh2(v0.x, v0.y);
                *(uint32_t*)&Ch[(size_t)(m0 + 8) * N + n0] = packh2(v1.x, v1.y);
            } else {
                *(float2*)&Cf[(size_t)m0 * N + n0]       = v0;
                *(float2*)&Cf[(size_t)(m0 + 8) * N + n0] = v1;
            }
        }
    }
}

// ---------------------------------------------------------------------------
// fp16 tensor-core flash attention (R12) + mask-flag register bitmask.
// ---------------------------------------------------------------------------
#define QT_ 128
#define QSTRB 160
#define KSTRB 160
#define VSTRB 144
#define QS_BYTES   (QT_ * QSTRB)
#define KSTG_BYTES (64 * KSTRB)
#define VSTG_BYTES (64 * VSTRB)
#define ATTN_SMEM_BYTES (QS_BYTES + 2 * KSTG_BYTES + 2 * VSTG_BYTES)  // 59,392

__global__ __launch_bounds__(256, 2)
void attn_h(const __half* __restrict__ QKV, const int* __restrict__ mask,
            const int* __restrict__ mflag, __half* __restrict__ O)
{
    extern __shared__ __align__(16) char smb[];
    const uint32_t sb  = smem_u32(smb);
    const uint32_t sQ  = sb;
    const uint32_t sK  = sb + QS_BYTES;
    const uint32_t sV  = sK + 2 * KSTG_BYTES;
    const char* Qsp = smb;
    const char* Ksp = smb + QS_BYTES;

    const int tid  = threadIdx.x;
    const int lane = tid & 31;
    const int wid  = tid >> 5;
    const int grp  = lane >> 2;
    const int qid  = lane & 3;

    const int qt = blockIdx.x;
    const int bh = blockIdx.y;
    const int b  = bh >> 4;
    const int h  = bh & 15;
    const int q0 = qt * QT_;

    const int LDQ = 3 * D_;
    const __half* Qb = QKV + (size_t)b * S_ * LDQ + (size_t)h * HD_;
    const __half* Kb = Qb + D_;
    const __half* Vb = Qb + 2 * D_;
    const int* mfbase = mflag + (b * (S_ / QT_) + qt) * (S_ / 64);

    // preload all 16 dirty flags into a bitmask
    uint32_t dirtymask = 0;
#pragma unroll
    for (int i = 0; i < S_ / 64; i++)
        dirtymask |= (mfbase[i] != 0) ? (1u << i) : 0u;

    auto issue_kv = [&](int kt, int buf) {
        const int k0g = kt * 64;
#pragma unroll
        for (int i = 0; i < 2; i++) {
            const int idx = tid + 256 * i;
            const int row = idx >> 3;
            const int ch  = idx & 7;
            cp_async16(sK + (uint32_t)buf * KSTG_BYTES + (uint32_t)row * KSTRB + ch * 16,
                       Kb + (size_t)(k0g + row) * LDQ + ch * 8);
            cp_async16(sV + (uint32_t)buf * VSTG_BYTES + (uint32_t)row * VSTRB + ch * 16,
                       Vb + (size_t)(k0g + row) * LDQ + ch * 8);
        }
        asm volatile("cp.async.commit_group;" ::: "memory");
    };

    issue_kv(0, 0);

#pragma unroll
    for (int i = 0; i < 4; i++) {
        const int idx = tid + 256 * i;
        const int row = idx >> 3;
        const int ch  = idx & 7;
        cp_async16(sQ + (uint32_t)row * QSTRB + ch * 16,
                   Qb + (size_t)(q0 + row) * LDQ + ch * 8);
    }
    asm volatile("cp.async.commit_group;" ::: "memory");

    const int qrow0 = wid * 16 + grp;
    const int* mrow0 = mask + (size_t)(b * S_ + q0 + qrow0) * S_;
    const int* mrow1 = mrow0 + 8 * S_;

    float mi0 = -1e30f, mi1 = -1e30f, li0 = 0.f, li1 = 0.f;
    float o[8][4];
#pragma unroll
    for (int nf = 0; nf < 8; nf++)
#pragma unroll
        for (int r = 0; r < 4; r++) o[nf][r] = 0.f;

    for (int kt = 0; kt < S_ / 64; kt++) {
        const int buf = kt & 1;
        const int k0  = kt * 64;
        const bool dirty = (dirtymask >> kt) & 1u;

        asm volatile("cp.async.wait_group 0;" ::: "memory");
        __syncthreads();

        if (kt + 1 < S_ / 64)
            issue_kv(kt + 1, buf ^ 1);

        const char* Kb2 = Ksp + (size_t)buf * KSTG_BYTES;
        const uint32_t Vb2 = sV + (uint32_t)buf * VSTG_BYTES;

        float c[8][4];
#pragma unroll
        for (int nf = 0; nf < 8; nf++)
#pragma unroll
            for (int r = 0; r < 4; r++) c[nf][r] = 0.f;

#pragma unroll
        for (int s = 0; s < 4; s++) {
            const uint2 lo = *(const uint2*)(Qsp + qrow0 * QSTRB + s * 32 + qid * 8);
            const uint2 hi = *(const uint2*)(Qsp + (qrow0 + 8) * QSTRB + s * 32 + qid * 8);
            uint32_t a[4] = { lo.x, hi.x, lo.y, hi.y };
#pragma unroll
            for (int nf = 0; nf < 8; nf++) {
                const uint2 bv = *(const uint2*)(Kb2 + (nf * 8 + grp) * KSTRB + s * 32 + qid * 8);
                uint32_t bb[2] = { bv.x, bv.y };
                mma_f16(c[nf], a, bb);
            }
        }

        if (dirty) {
#pragma unroll
            for (int nf = 0; nf < 8; nf++) {
                const int kc = k0 + nf * 8 + 2 * qid;
                const int2 m0 = *(const int2*)&mrow0[kc];
                const int2 m1 = *(const int2*)&mrow1[kc];
                if (m0.x == 0) c[nf][0] = -1e8f;
                if (m0.y == 0) c[nf][1] = -1e8f;
                if (m1.x == 0) c[nf][2] = -1e8f;
                if (m1.y == 0) c[nf][3] = -1e8f;
            }
        }

        float mx0 = -1e30f, mx1 = -1e30f;
#pragma unroll
        for (int nf = 0; nf < 8; nf++) {
            mx0 = fmaxf(mx0, fmaxf(c[nf][0], c[nf][1]));
            mx1 = fmaxf(mx1, fmaxf(c[nf][2], c[nf][3]));
        }
        mx0 = fmaxf(mx0, __shfl_xor_sync(0xffffffffu, mx0, 1));
        mx0 = fmaxf(mx0, __shfl_xor_sync(0xffffffffu, mx0, 2));
        mx1 = fmaxf(mx1, __shfl_xor_sync(0xffffffffu, mx1, 1));
        mx1 = fmaxf(mx1, __shfl_xor_sync(0xffffffffu, mx1, 2));

        const float mn0 = fmaxf(mi0, mx0);
        const float mn1 = fmaxf(mi1, mx1);
        const float al0 = __expf(mi0 - mn0);
        const float al1 = __expf(mi1 - mn1);

        float sum0 = 0.f, sum1 = 0.f;
#pragma unroll
        for (int nf = 0; nf < 8; nf++) {
            float e;
            e = __expf(c[nf][0] - mn0); sum0 += e; c[nf][0] = e;
            e = __expf(c[nf][1] - mn0); sum0 += e; c[nf][1] = e;
            e = __expf(c[nf][2] - mn1); sum1 += e; c[nf][2] = e;
            e = __expf(c[nf][3] - mn1); sum1 += e; c[nf][3] = e;
        }
        sum0 += __shfl_xor_sync(0xffffffffu, sum0, 1);
        sum0 += __shfl_xor_sync(0xffffffffu, sum0, 2);
        sum1 += __shfl_xor_sync(0xffffffffu, sum1, 1);
        sum1 += __shfl_xor_sync(0xffffffffu, sum1, 2);

        li0 = li0 * al0 + sum0;  mi0 = mn0;
        li1 = li1 * al1 + sum1;  mi1 = mn1;

#pragma unroll
        for (int nf = 0; nf < 8; nf++) {
            o[nf][0] *= al0; o[nf][1] *= al0;
            o[nf][2] *= al1; o[nf][3] *= al1;
        }

        const int lmi = lane >> 3;
        const int lmr = lane & 7;
#pragma unroll
        for (int s = 0; s < 4; s++) {
            uint32_t a[4];
            a[0] = packh2(c[2 * s][0],     c[2 * s][1]);
            a[1] = packh2(c[2 * s][2],     c[2 * s][3]);
            a[2] = packh2(c[2 * s + 1][0], c[2 * s + 1][1]);
            a[3] = packh2(c[2 * s + 1][2], c[2 * s + 1][3]);
#pragma unroll
            for (int nfp = 0; nfp < 4; nfp++) {
                const int vrow = 16 * s + ((lmi & 1) << 3) + lmr;
                const int vcol = 16 * nfp + ((lmi >> 1) << 3);
                uint32_t b0, b1, b2, b3;
                ldsm_x4_t(b0, b1, b2, b3,
                          Vb2 + (uint32_t)vrow * VSTRB + (uint32_t)vcol * 2);
                { uint32_t bb[2] = { b0, b1 }; mma_f16(o[2 * nfp],     a, bb); }
                { uint32_t bb[2] = { b2, b3 }; mma_f16(o[2 * nfp + 1], a, bb); }
            }
        }
    }

    const float inv0 = 1.0f / li0;
    const float inv1 = 1.0f / li1;
    __half* row0g = O + (size_t)(b * S_ + q0 + qrow0) * D_ + (size_t)h * HD_;
    __half* row1g = row0g + (size_t)8 * D_;
#pragma unroll
    for (int nf = 0; nf < 8; nf++) {
        const int d0 = nf * 8 + 2 * qid;
        *(uint32_t*)(row0g + d0) = packh2(o[nf][0] * inv0, o[nf][1] * inv0);
        *(uint32_t*)(row1g + d0) = packh2(o[nf][2] * inv1, o[nf][3] * inv1);
    }
}

// ---------------------------------------------------------------------------
// Launch.  Inputs: x, Wq, bq, Wk, bk, Wv, bv, W1, b1, W2, b2, mask
// ---------------------------------------------------------------------------
extern "C" void kernel_launch(void* const* d_in, const int* in_sizes, int n_in,
                              void* d_out, int out_size)
{
    const float* x    = (const float*)d_in[0];
    const float* Wq   = (const float*)d_in[1];
    const float* bq   = (const float*)d_in[2];
    const float* Wk   = (const float*)d_in[3];
    const float* bk   = (const float*)d_in[4];
    const float* Wv   = (const float*)d_in[5];
    const float* bv   = (const float*)d_in[6];
    const float* W1   = (const float*)d_in[7];
    const float* b1   = (const float*)d_in[8];
    const float* W2   = (const float*)d_in[9];
    const float* b2   = (const float*)d_in[10];
    const int*   mask = (const int*)d_in[11];
    float*       out  = (float*)d_out;

    __half *Xh, *Wqkvh, *W1h, *W2h, *QKVh, *Chp, *Hhp;
    float *bqkvp;
    int *mflagp;
    cudaGetSymbolAddress((void**)&Xh,     g_Xh);
    cudaGetSymbolAddress((void**)&Wqkvh,  g_Wqkvh);
    cudaGetSymbolAddress((void**)&W1h,    g_W1h);
    cudaGetSymbolAddress((void**)&W2h,    g_W2h);
    cudaGetSymbolAddress((void**)&QKVh,   g_QKVh);
    cudaGetSymbolAddress((void**)&Chp,    g_Ch);
    cudaGetSymbolAddress((void**)&Hhp,    g_Hh);
    cudaGetSymbolAddress((void**)&bqkvp,  g_bqkv);
    cudaGetSymbolAddress((void**)&mflagp, g_mflag);

    cudaFuncSetAttribute(attn_h,
                         cudaFuncAttributeMaxDynamicSharedMemorySize, ATTN_SMEM_BYTES);
    cudaFuncSetAttribute((const void*)gemm_h<0>,
                         cudaFuncAttributeMaxDynamicSharedMemorySize, HGEMM_SMEM);
    cudaFuncSetAttribute((const void*)gemm_h<1>,
                         cudaFuncAttributeMaxDynamicSharedMemorySize, HGEMM_SMEM);
    cudaFuncSetAttribute((const void*)gemm_h<2>,
                         cudaFuncAttributeMaxDynamicSharedMemorySize, HGEMM_SMEM);

    const dim3 blk(256);
    const int T = 256;

    // ---- prep ----
    HSegs P;
    P.src[0] = x;  P.dst[0] = Xh;
    P.src[1] = Wq; P.dst[1] = Wqkvh;
    P.src[2] = Wk; P.dst[2] = Wqkvh + (size_t)D_ * D_;
    P.src[3] = Wv; P.dst[3] = Wqkvh + (size_t)2 * D_ * D_;
    P.src[4] = W1; P.dst[4] = W1h;
    P.src[5] = W2; P.dst[5] = W2h;
    const int gr[6] = { M_ * D_ / 16, D_ * D_ / 16, D_ * D_ / 16, D_ * D_ / 16,
                        2 * D_ * D_ / 16, 2 * D_ * D_ / 16 };
    P.cum[0] = 0;
    for (int j = 0; j < 6; j++) P.cum[j + 1] = P.cum[j] + gr[j];
    round_half_all<<<(P.cum[6] + 511) / 512, 512>>>(P);
    concat_bias<<<(3 * D_ + T - 1) / T, T>>>(bq, bk, bv, bqkvp);
    mask_scan<<<B_ * (S_ / 128) * (S_ / 64), T>>>(mask, mflagp);

    // ---- fused QKV projection ----
    gemm_h<0><<<dim3(3 * D_ / 128, M_ / 128), blk, HGEMM_SMEM>>>(
        Xh, Wqkvh, bqkvp, (float*)nullptr, QKVh, M_, 3 * D_, D_);

    // ---- attention ----
    attn_h<<<dim3(S_ / QT_, B_ * H_), blk, ATTN_SMEM_BYTES>>>(QKVh, mask, mflagp, Chp);

    // ---- MLP ----
    gemm_h<1><<<dim3(2 * D_ / 128, M_ / 128), blk, HGEMM_SMEM>>>(
        Chp, W1h, b1, (float*)nullptr, Hhp, M_, 2 * D_, D_);
    gemm_h<2><<<dim3(D_ / 128, M_ / 128), blk, HGEMM_SMEM>>>(
        Hhp, W2h, b2, out, (__half*)nullptr, M_, D_, 2 * D_);
}

// round 16
// speedup vs baseline: 1.6564x; 1.0006x over previous
#include <cuda_runtime.h>
#include <cuda_fp16.h>
#include <stdint.h>

#define B_  4
#define S_  1024
#define D_  1024
#define H_  16
#define HD_ 64
#define M_  (B_ * S_)     // 4096

// ---------------------------------------------------------------------------
// Scratch (device globals)
// ---------------------------------------------------------------------------
__device__ __align__(16) __half g_Xh   [(size_t)M_ * D_];
__device__ __align__(16) __half g_Wqkvh[(size_t)3 * D_ * D_];
__device__ __align__(16) __half g_W1h  [(size_t)2 * D_ * D_];
__device__ __align__(16) __half g_W2h  [(size_t)2 * D_ * D_];
__device__ __align__(16) __half g_QKVh [(size_t)M_ * 3 * D_];    // Q,K,V all plain fp16
__device__ __align__(16) __half g_Ch   [(size_t)M_ * D_];
__device__ __align__(16) __half g_Hh   [(size_t)M_ * 2 * D_];
__device__ __align__(16) float  g_bqkv [3 * D_];
__device__ int g_mflag[B_ * (S_ / 128) * (S_ / 64)];

// ---------------------------------------------------------------------------
__device__ __forceinline__ void mma_f16(float* c, const uint32_t* a, const uint32_t* b) {
    asm volatile(
        "mma.sync.aligned.m16n8k16.row.col.f32.f16.f16.f32 "
        "{%0,%1,%2,%3}, {%4,%5,%6,%7}, {%8,%9}, {%0,%1,%2,%3};\n"
        : "+f"(c[0]), "+f"(c[1]), "+f"(c[2]), "+f"(c[3])
        : "r"(a[0]), "r"(a[1]), "r"(a[2]), "r"(a[3]), "r"(b[0]), "r"(b[1]));
}

__device__ __forceinline__ void ldsm_x4(uint32_t& r0, uint32_t& r1,
                                        uint32_t& r2, uint32_t& r3, uint32_t addr) {
    asm volatile("ldmatrix.sync.aligned.m8n8.x4.shared.b16 {%0,%1,%2,%3}, [%4];"
                 : "=r"(r0), "=r"(r1), "=r"(r2), "=r"(r3) : "r"(addr));
}

__device__ __forceinline__ void ldsm_x4_t(uint32_t& r0, uint32_t& r1,
                                          uint32_t& r2, uint32_t& r3, uint32_t addr) {
    asm volatile("ldmatrix.sync.aligned.m8n8.x4.trans.shared.b16 {%0,%1,%2,%3}, [%4];"
                 : "=r"(r0), "=r"(r1), "=r"(r2), "=r"(r3) : "r"(addr));
}

__device__ __forceinline__ uint32_t smem_u32(const void* p) {
    uint32_t a;
    asm("{ .reg .u64 t; cvta.to.shared.u64 t, %1; cvt.u32.u64 %0, t; }"
        : "=r"(a) : "l"(p));
    return a;
}

__device__ __forceinline__ void cp_async16(uint32_t dst, const void* src) {
    asm volatile("cp.async.cg.shared.global [%0], [%1], 16;"
                 :: "r"(dst), "l"(src) : "memory");
}

__device__ __forceinline__ uint32_t packh2(float x, float y) {
    __half2 h = __floats2half2_rn(x, y);
    return *(uint32_t*)&h;
}

// ---------------------------------------------------------------------------
// Prep kernels
// ---------------------------------------------------------------------------
struct HSegs {
    const float* src[6];
    __half*      dst[6];
    int          cum[7];
};

__global__ void round_half_all(HSegs P) {
    const int i = blockIdx.x * blockDim.x + threadIdx.x;
    if (i >= P.cum[6]) return;
#pragma unroll
    for (int j = 0; j < 6; j++) {
        if (i < P.cum[j + 1]) {
            const int g = i - P.cum[j];
            const float4* s = (const float4*)P.src[j] + (size_t)g * 4;
            float l[16];
            *(float4*)&l[0]  = s[0];
            *(float4*)&l[4]  = s[1];
            *(float4*)&l[8]  = s[2];
            *(float4*)&l[12] = s[3];
            uint4 o0, o1;
            o0.x = packh2(l[0],  l[1]);  o0.y = packh2(l[2],  l[3]);
            o0.z = packh2(l[4],  l[5]);  o0.w = packh2(l[6],  l[7]);
            o1.x = packh2(l[8],  l[9]);  o1.y = packh2(l[10], l[11]);
            o1.z = packh2(l[12], l[13]); o1.w = packh2(l[14], l[15]);
            uint4* d = (uint4*)(P.dst[j] + (size_t)g * 16);
            d[0] = o0; d[1] = o1;
            return;
        }
    }
}

__global__ void concat_bias(const float* __restrict__ a, const float* __restrict__ b,
                            const float* __restrict__ c, float* __restrict__ dst) {
    const int i = blockIdx.x * blockDim.x + threadIdx.x;
    if (i < 3 * D_)
        dst[i] = (i < D_) ? a[i] : ((i < 2 * D_) ? b[i - D_] : c[i - 2 * D_]);
}

__global__ __launch_bounds__(256)
void mask_scan(const int* __restrict__ mask, int* __restrict__ flags) {
    const int fidx = blockIdx.x;
    const int kt = fidx & 15;
    const int qt = (fidx >> 4) & 7;
    const int b  = fidx >> 7;
    const int q0 = qt * 128;
    const int k0 = kt * 64;
    const int tid = threadIdx.x;

    int ok = 1;
#pragma unroll
    for (int i = 0; i < 8; i++) {
        const int idx = tid + 256 * i;
        const int row = idx >> 4;
        const int c4  = (idx & 15) * 4;
        const int4 v = *(const int4*)&mask[((size_t)(b * S_ + q0 + row)) * S_ + k0 + c4];
        if (v.x == 0 || v.y == 0 || v.z == 0 || v.w == 0) ok = 0;
    }
    const int all_ok = __syncthreads_and(ok);
    if (tid == 0) flags[fidx] = !all_ok;
}

// ---------------------------------------------------------------------------
// fp16 tensor-core GEMM (R12 exact): 128x128 tile, K-stage 64, 3-stage
// cp.async, XOR-swizzled smem + ldmatrix fragment loads, 2 CTAs/SM.
// MODE: 0 = QKV (fp16 out, Q prescale, all plain), 1 = MLP1 (ReLU, fp16 out),
//       2 = MLP2 (fp32 out).
// ---------------------------------------------------------------------------
#define GROWB 128
#define GSTG_B (128 * GROWB)
#define GSTAGE_B (2 * GSTG_B)
#define GNST 3
#define HGEMM_SMEM (GNST * GSTAGE_B)   // 98,304

template <int MODE>
__global__ __launch_bounds__(256, 2)
void gemm_h(const __half* __restrict__ A, const __half* __restrict__ Bm,
            const float* __restrict__ bias, float* __restrict__ Cf,
            __half* __restrict__ Ch, int M, int N, int K)
{
    extern __shared__ __align__(16) char smc[];
    const uint32_t sb = smem_u32(smc);

    const int tid  = threadIdx.x;
    const int lane = tid & 31;
    const int wid  = tid >> 5;
    const int wm   = wid >> 2;
    const int wn   = wid & 3;
    const int grp  = lane >> 2;
    const int qid  = lane & 3;

    const int bm = blockIdx.y * 128;
    const int bn = blockIdx.x * 128;

    const __half* AgBase = A  + (size_t)bm * K;
    const __half* BgBase = Bm + (size_t)bn * K;

    auto issue_stage = [&](int stage, int buf) {
        const int k0 = stage * 64;
        const uint32_t sA = sb + (uint32_t)buf * GSTAGE_B;
        const uint32_t sB = sA + GSTG_B;
#pragma unroll
        for (int i = 0; i < 4; i++) {
            const int ci  = tid + 256 * i;
            const int row = ci >> 3;
            const int c   = ci & 7;
            cp_async16(sA + (uint32_t)row * GROWB + (uint32_t)((c ^ (row & 7)) << 4),
                       AgBase + (size_t)row * K + k0 + c * 8);
        }
#pragma unroll
        for (int i = 0; i < 4; i++) {
            const int ci  = tid + 256 * i;
            const int row = ci >> 3;
            const int c   = ci & 7;
            cp_async16(sB + (uint32_t)row * GROWB + (uint32_t)((c ^ (row & 7)) << 4),
                       BgBase + (size_t)row * K + k0 + c * 8);
        }
        asm volatile("cp.async.commit_group;" ::: "memory");
    };

    float acc[4][4][4];
#pragma unroll
    for (int i = 0; i < 4; i++)
#pragma unroll
        for (int j = 0; j < 4; j++)
#pragma unroll
            for (int r = 0; r < 4; r++) acc[i][j][r] = 0.f;

    const int KT = K / 64;

    issue_stage(0, 0);
    issue_stage(1, 1);

    const int al8 = (lane & 7) + ((lane >> 3) & 1) * 8;
    const int ach = lane >> 4;
    const int bl8 = lane & 7;
    const int bg  = lane >> 3;

    for (int kt = 0; kt < KT; kt++) {
        const int buf = kt % GNST;

        if (kt < KT - 1)
            asm volatile("cp.async.wait_group 1;" ::: "memory");
        else
            asm volatile("cp.async.wait_group 0;" ::: "memory");
        __syncthreads();

        if (kt + 2 < KT)
            issue_stage(kt + 2, (kt + 2) % GNST);

        const uint32_t sA = sb + (uint32_t)buf * GSTAGE_B;
        const uint32_t sB = sA + GSTG_B;

#pragma unroll
        for (int s = 0; s < 4; s++) {
            uint32_t a[4][4];
#pragma unroll
            for (int mf = 0; mf < 4; mf++) {
                const int arow = wm * 64 + mf * 16 + al8;
                const int c    = (s * 2 + ach) ^ (arow & 7);
                ldsm_x4(a[mf][0], a[mf][1], a[mf][2], a[mf][3],
                        sA + (uint32_t)arow * GROWB + (uint32_t)(c << 4));
            }
            uint32_t b[4][2];
#pragma unroll
            for (int nfp = 0; nfp < 2; nfp++) {
                const int brow = wn * 32 + nfp * 16 + (bg >> 1) * 8 + bl8;
                const int c    = (s * 2 + (bg & 1)) ^ (brow & 7);
                ldsm_x4(b[2 * nfp][0], b[2 * nfp][1], b[2 * nfp + 1][0], b[2 * nfp + 1][1],
                        sB + (uint32_t)brow * GROWB + (uint32_t)(c << 4));
            }
#pragma unroll
            for (int mf = 0; mf < 4; mf++)
#pragma unroll
                for (int nf = 0; nf < 4; nf++)
                    mma_f16(acc[mf][nf], a[mf], b[nf]);
        }
    }

    // ---- Epilogue ----
#pragma unroll
    for (int mf = 0; mf < 4; mf++) {
#pragma unroll
        for (int nf = 0; nf < 4; nf++) {
            const int m0 = bm + wm * 64 + mf * 16 + grp;
            const int n0 = bn + wn * 32 + nf * 8 + 2 * qid;
            const float bx = bias[n0], by = bias[n0 + 1];
            float2 v0, v1;
            v0.x = acc[mf][nf][0] + bx; v0.y = acc[mf][nf][1] + by;
            v1.x = acc[mf][nf][2] + bx; v1.y = acc[mf][nf][3] + by;

            if (MODE == 0) {
                if (n0 < D_) {
                    v0.x *= 0.125f; v0.y *= 0.125f;
                    v1.x *= 0.125f; v1.y *= 0.125f;
                }
                *(uint32_t*)&Ch[(size_t)m0 * N + n0]       = packh2(v0.x, v0.y);
                *(uint32_t*)&Ch[(size_t)(m0 + 8) * N + n0] = packh2(v1.x, v1.y);
            } else if (MODE == 1) {
                v0.x = fmaxf(v0.x, 0.f); v0.y = fmaxf(v0.y, 0.f);
                v1.x = fmaxf(v1.x, 0.f); v1.y = fmaxf(v1.y, 0.f);
                *(uint32_t*)&Ch[(size_t)m0 * N + n0]       = packh2(v0.x, v0.y);
                *(uint32_t*)&Ch[(size_t)(m0 + 8) * N + n0] = packh2(v1.x, v1.y);
            } else {
                *(float2*)&Cf[(size_t)m0 * N + n0]       = v0;
                *(float2*)&Cf[(size_t)(m0 + 8) * N + n0] = v1;
            }
        }
    }
}

// ---------------------------------------------------------------------------
// fp16 tensor-core flash attention: Q,K,V plain fp16, 144B row stride,
// ldmatrix.x4 fragment loads everywhere, mask dirty-flag bitmask.
// ---------------------------------------------------------------------------
#define QT_ 128
#define QSTRB 144
#define KSTRB 144
#define VSTRB 144
#define QS_BYTES   (QT_ * QSTRB)          // 18,432
#define KSTG_BYTES (64 * KSTRB)           //  9,216
#define VSTG_BYTES (64 * VSTRB)           //  9,216
#define ATTN_SMEM_BYTES (QS_BYTES + 2 * KSTG_BYTES + 2 * VSTG_BYTES)  // 55,296

__global__ __launch_bounds__(256, 2)
void attn_h(const __half* __restrict__ QKV, const int* __restrict__ mask,
            const int* __restrict__ mflag, __half* __restrict__ O)
{
    extern __shared__ __align__(16) char smb[];
    const uint32_t sb  = smem_u32(smb);
    const uint32_t sQ  = sb;
    const uint32_t sK  = sb + QS_BYTES;
    const uint32_t sV  = sK + 2 * KSTG_BYTES;

    const int tid  = threadIdx.x;
    const int lane = tid & 31;
    const int wid  = tid >> 5;
    const int grp  = lane >> 2;
    const int qid  = lane & 3;

    const int qt = blockIdx.x;
    const int bh = blockIdx.y;
    const int b  = bh >> 4;
    const int h  = bh & 15;
    const int q0 = qt * QT_;

    const int LDQ = 3 * D_;
    const __half* Qb = QKV + (size_t)b * S_ * LDQ + (size_t)h * HD_;
    const __half* Kb = Qb + D_;
    const __half* Vb = Qb + 2 * D_;
    const int* mfbase = mflag + (b * (S_ / QT_) + qt) * (S_ / 64);

    // preload all 16 dirty flags into a bitmask
    uint32_t dirtymask = 0;
#pragma unroll
    for (int i = 0; i < S_ / 64; i++)
        dirtymask |= (mfbase[i] != 0) ? (1u << i) : 0u;

    auto issue_kv = [&](int kt, int buf) {
        const int k0g = kt * 64;
#pragma unroll
        for (int i = 0; i < 2; i++) {
            const int idx = tid + 256 * i;
            const int row = idx >> 3;
            const int ch  = idx & 7;
            cp_async16(sK + (uint32_t)buf * KSTG_BYTES + (uint32_t)row * KSTRB + ch * 16,
                       Kb + (size_t)(k0g + row) * LDQ + ch * 8);
            cp_async16(sV + (uint32_t)buf * VSTG_BYTES + (uint32_t)row * VSTRB + ch * 16,
                       Vb + (size_t)(k0g + row) * LDQ + ch * 8);
        }
        asm volatile("cp.async.commit_group;" ::: "memory");
    };

    issue_kv(0, 0);

    // Q tile: raw copy (pre-scaled upstream), plain layout
#pragma unroll
    for (int i = 0; i < 4; i++) {
        const int idx = tid + 256 * i;
        const int row = idx >> 3;
        const int ch  = idx & 7;
        cp_async16(sQ + (uint32_t)row * QSTRB + ch * 16,
                   Qb + (size_t)(q0 + row) * LDQ + ch * 8);
    }
    asm volatile("cp.async.commit_group;" ::: "memory");

    const int qrow0 = wid * 16 + grp;
    const int* mrow0 = mask + (size_t)(b * S_ + q0 + qrow0) * S_;
    const int* mrow1 = mrow0 + 8 * S_;

    // ldmatrix lane-address components
    const int aRowL   = wid * 16 + (lane & 7) + ((lane >> 3) & 1) * 8;
    const uint32_t aCo = (uint32_t)((lane >> 4) & 1) * 16;   // bytes
    const int bRowL   = (lane & 7) + ((lane >> 4) & 1) * 8;
    const uint32_t bCo = (uint32_t)((lane >> 3) & 1) * 16;   // bytes

    float mi0 = -1e30f, mi1 = -1e30f, li0 = 0.f, li1 = 0.f;
    float o[8][4];
#pragma unroll
    for (int nf = 0; nf < 8; nf++)
#pragma unroll
        for (int r = 0; r < 4; r++) o[nf][r] = 0.f;

    for (int kt = 0; kt < S_ / 64; kt++) {
        const int buf = kt & 1;
        const int k0  = kt * 64;
        const bool dirty = (dirtymask >> kt) & 1u;

        asm volatile("cp.async.wait_group 0;" ::: "memory");
        __syncthreads();

        if (kt + 1 < S_ / 64)
            issue_kv(kt + 1, buf ^ 1);

        const uint32_t sKb = sK + (uint32_t)buf * KSTG_BYTES;
        const uint32_t sVb = sV + (uint32_t)buf * VSTG_BYTES;

        // ---- QK^T: ldmatrix.x4 fragments ----
        float c[8][4];
#pragma unroll
        for (int nf = 0; nf < 8; nf++)
#pragma unroll
            for (int r = 0; r < 4; r++) c[nf][r] = 0.f;

#pragma unroll
        for (int s = 0; s < 4; s++) {
            uint32_t a[4];
            ldsm_x4(a[0], a[1], a[2], a[3],
                    sQ + (uint32_t)aRowL * QSTRB + (uint32_t)s * 32 + aCo);
            uint32_t bf[8][2];
#pragma unroll
            for (int nfp = 0; nfp < 4; nfp++) {
                ldsm_x4(bf[2 * nfp][0], bf[2 * nfp][1],
                        bf[2 * nfp + 1][0], bf[2 * nfp + 1][1],
                        sKb + (uint32_t)(nfp * 16 + bRowL) * KSTRB + (uint32_t)s * 32 + bCo);
            }
#pragma unroll
            for (int nf = 0; nf < 8; nf++)
                mma_f16(c[nf], a, bf[nf]);
        }

        // ---- mask (only when this tile has zeros) ----
        if (dirty) {
#pragma unroll
            for (int nf = 0; nf < 8; nf++) {
                const int kc = k0 + nf * 8 + 2 * qid;
                const int2 m0 = *(const int2*)&mrow0[kc];
                const int2 m1 = *(const int2*)&mrow1[kc];
                if (m0.x == 0) c[nf][0] = -1e8f;
                if (m0.y == 0) c[nf][1] = -1e8f;
                if (m1.x == 0) c[nf][2] = -1e8f;
                if (m1.y == 0) c[nf][3] = -1e8f;
            }
        }

        // ---- online softmax on fragments ----
        float mx0 = -1e30f, mx1 = -1e30f;
#pragma unroll
        for (int nf = 0; nf < 8; nf++) {
            mx0 = fmaxf(mx0, fmaxf(c[nf][0], c[nf][1]));
            mx1 = fmaxf(mx1, fmaxf(c[nf][2], c[nf][3]));
        }
        mx0 = fmaxf(mx0, __shfl_xor_sync(0xffffffffu, mx0, 1));
        mx0 = fmaxf(mx0, __shfl_xor_sync(0xffffffffu, mx0, 2));
        mx1 = fmaxf(mx1, __shfl_xor_sync(0xffffffffu, mx1, 1));
        mx1 = fmaxf(mx1, __shfl_xor_sync(0xffffffffu, mx1, 2));

        const float mn0 = fmaxf(mi0, mx0);
        const float mn1 = fmaxf(mi1, mx1);
        const float al0 = __expf(mi0 - mn0);
        const float al1 = __expf(mi1 - mn1);

        float sum0 = 0.f, sum1 = 0.f;
#pragma unroll
        for (int nf = 0; nf < 8; nf++) {
            float e;
            e = __expf(c[nf][0] - mn0); sum0 += e; c[nf][0] = e;
            e = __expf(c[nf][1] - mn0); sum0 += e; c[nf][1] = e;
            e = __expf(c[nf][2] - mn1); sum1 += e; c[nf][2] = e;
            e = __expf(c[nf][3] - mn1); sum1 += e; c[nf][3] = e;
        }
        sum0 += __shfl_xor_sync(0xffffffffu, sum0, 1);
        sum0 += __shfl_xor_sync(0xffffffffu, sum0, 2);
        sum1 += __shfl_xor_sync(0xffffffffu, sum1, 1);
        sum1 += __shfl_xor_sync(0xffffffffu, sum1, 2);

        li0 = li0 * al0 + sum0;  mi0 = mn0;
        li1 = li1 * al1 + sum1;  mi1 = mn1;

#pragma unroll
        for (int nf = 0; nf < 8; nf++) {
            o[nf][0] *= al0; o[nf][1] *= al0;
            o[nf][2] *= al1; o[nf][3] *= al1;
        }

        // ---- PV: V via ldmatrix.trans (unchanged) ----
        const int lmi = lane >> 3;
        const int lmr = lane & 7;
#pragma unroll
        for (int s = 0; s < 4; s++) {
            uint32_t a[4];
            a[0] = packh2(c[2 * s][0],     c[2 * s][1]);
            a[1] = packh2(c[2 * s][2],     c[2 * s][3]);
            a[2] = packh2(c[2 * s + 1][0], c[2 * s + 1][1]);
            a[3] = packh2(c[2 * s + 1][2], c[2 * s + 1][3]);
#pragma unroll
            for (int nfp = 0; nfp < 4; nfp++) {
                const int vrow = 16 * s + ((lmi & 1) << 3) + lmr;
                const int vcol = 16 * nfp + ((lmi >> 1) << 3);
                uint32_t b0, b1, b2, b3;
                ldsm_x4_t(b0, b1, b2, b3,
                          sVb + (uint32_t)vrow * VSTRB + (uint32_t)vcol * 2);
                { uint32_t bb[2] = { b0, b1 }; mma_f16(o[2 * nfp],     a, bb); }
                { uint32_t bb[2] = { b2, b3 }; mma_f16(o[2 * nfp + 1], a, bb); }
            }
        }
    }

    // ---- finalize: ctx standard fp16 ----
    const float inv0 = 1.0f / li0;
    const float inv1 = 1.0f / li1;
    __half* row0g = O + (size_t)(b * S_ + q0 + qrow0) * D_ + (size_t)h * HD_;
    __half* row1g = row0g + (size_t)8 * D_;
#pragma unroll
    for (int nf = 0; nf < 8; nf++) {
        const int d0 = nf * 8 + 2 * qid;
        *(uint32_t*)(row0g + d0) = packh2(o[nf][0] * inv0, o[nf][1] * inv0);
        *(uint32_t*)(row1g + d0) = packh2(o[nf][2] * inv1, o[nf][3] * inv1);
    }
}

// ---------------------------------------------------------------------------
// Launch.  Inputs: x, Wq, bq, Wk, bk, Wv, bv, W1, b1, W2, b2, mask
// ---------------------------------------------------------------------------
extern "C" void kernel_launch(void* const* d_in, const int* in_sizes, int n_in,
                              void* d_out, int out_size)
{
    const float* x    = (const float*)d_in[0];
    const float* Wq   = (const float*)d_in[1];
    const float* bq   = (const float*)d_in[2];
    const float* Wk   = (const float*)d_in[3];
    const float* bk   = (const float*)d_in[4];
    const float* Wv   = (const float*)d_in[5];
    const float* bv   = (const float*)d_in[6];
    const float* W1   = (const float*)d_in[7];
    const float* b1   = (const float*)d_in[8];
    const float* W2   = (const float*)d_in[9];
    const float* b2   = (const float*)d_in[10];
    const int*   mask = (const int*)d_in[11];
    float*       out  = (float*)d_out;

    __half *Xh, *Wqkvh, *W1h, *W2h, *QKVh, *Chp, *Hhp;
    float *bqkvp;
    int *mflagp;
    cudaGetSymbolAddress((void**)&Xh,     g_Xh);
    cudaGetSymbolAddress((void**)&Wqkvh,  g_Wqkvh);
    cudaGetSymbolAddress((void**)&W1h,    g_W1h);
    cudaGetSymbolAddress((void**)&W2h,    g_W2h);
    cudaGetSymbolAddress((void**)&QKVh,   g_QKVh);
    cudaGetSymbolAddress((void**)&Chp,    g_Ch);
    cudaGetSymbolAddress((void**)&Hhp,    g_Hh);
    cudaGetSymbolAddress((void**)&bqkvp,  g_bqkv);
    cudaGetSymbolAddress((void**)&mflagp, g_mflag);

    cudaFuncSetAttribute(attn_h,
                         cudaFuncAttributeMaxDynamicSharedMemorySize, ATTN_SMEM_BYTES);
    cudaFuncSetAttribute((const void*)gemm_h<0>,
                         cudaFuncAttributeMaxDynamicSharedMemorySize, HGEMM_SMEM);
    cudaFuncSetAttribute((const void*)gemm_h<1>,
                         cudaFuncAttributeMaxDynamicSharedMemorySize, HGEMM_SMEM);
    cudaFuncSetAttribute((const void*)gemm_h<2>,
                         cudaFuncAttributeMaxDynamicSharedMemorySize, HGEMM_SMEM);

    const dim3 blk(256);
    const int T = 256;

    // ---- prep ----
    HSegs P;
    P.src[0] = x;  P.dst[0] = Xh;
    P.src[1] = Wq; P.dst[1] = Wqkvh;
    P.src[2] = Wk; P.dst[2] = Wqkvh + (size_t)D_ * D_;
    P.src[3] = Wv; P.dst[3] = Wqkvh + (size_t)2 * D_ * D_;
    P.src[4] = W1; P.dst[4] = W1h;
    P.src[5] = W2; P.dst[5] = W2h;
    const int gr[6] = { M_ * D_ / 16, D_ * D_ / 16, D_ * D_ / 16, D_ * D_ / 16,
                        2 * D_ * D_ / 16, 2 * D_ * D_ / 16 };
    P.cum[0] = 0;
    for (int j = 0; j < 6; j++) P.cum[j + 1] = P.cum[j] + gr[j];
    round_half_all<<<(P.cum[6] + 511) / 512, 512>>>(P);
    concat_bias<<<(3 * D_ + T - 1) / T, T>>>(bq, bk, bv, bqkvp);
    mask_scan<<<B_ * (S_ / 128) * (S_ / 64), T>>>(mask, mflagp);

    // ---- fused QKV projection ----
    gemm_h<0><<<dim3(3 * D_ / 128, M_ / 128), blk, HGEMM_SMEM>>>(
        Xh, Wqkvh, bqkvp, (float*)nullptr, QKVh, M_, 3 * D_, D_);

    // ---- attention ----
    attn_h<<<dim3(S_ / QT_, B_ * H_), blk, ATTN_SMEM_BYTES>>>(QKVh, mask, mflagp, Chp);

    // ---- MLP ----
    gemm_h<1><<<dim3(2 * D_ / 128, M_ / 128), blk, HGEMM_SMEM>>>(
        Chp, W1h, b1, (float*)nullptr, Hhp, M_, 2 * D_, D_);
    gemm_h<2><<<dim3(D_ / 128, M_ / 128), blk, HGEMM_SMEM>>>(
        Hhp, W2h, b2, out, (__half*)nullptr, M_, D_, 2 * D_);
}